// round 10
// baseline (speedup 1.0000x reference)
#include <cuda_runtime.h>
#include <cuda_fp16.h>
#include <math.h>
#include <stdint.h>

#define S_DIM 128
#define R_DIM 256
#define C_DIM 256
#define H_DIM 8
#define D_DIM 32
#define HD_DIM 256
#define SR_DIM (S_DIM * R_DIM)

// Scratch (device globals; allocation-free contract)
__device__ float  g_Q[S_DIM * H_DIM * R_DIM * D_DIM];   // [s][h][r][d] fp32
__device__ float  g_K[S_DIM * H_DIM * R_DIM * D_DIM];
__device__ float  g_V[S_DIM * H_DIM * R_DIM * D_DIM];
__device__ float  g_G[S_DIM * H_DIM * R_DIM * D_DIM];
__device__ float  g_biasT[H_DIM * R_DIM * R_DIM];       // [h][q][k]
__device__ __half g_qh[SR_DIM * 256];                   // q input, half
__device__ __half g_kvh[SR_DIM * 256];                  // kv input, half
__device__ __half g_Oh[S_DIM * H_DIM * R_DIM * D_DIM];  // gated O, half
__device__ __half g_WTh[5 * 256 * 256];                 // weights transposed [n][k], half

// ---------------------------------------------------------------------------
// helpers
// ---------------------------------------------------------------------------
__device__ __forceinline__ uint32_t f2tf(float f) {
    uint32_t u;
    asm("cvt.rna.tf32.f32 %0, %1;" : "=r"(u) : "f"(f));
    return u;
}

__device__ __forceinline__ void mma_tf32(float c[4],
                                         uint32_t a0, uint32_t a1,
                                         uint32_t a2, uint32_t a3,
                                         uint32_t b0, uint32_t b1) {
    asm volatile(
        "mma.sync.aligned.m16n8k8.row.col.f32.tf32.tf32.f32 "
        "{%0,%1,%2,%3}, {%4,%5,%6,%7}, {%8,%9}, {%0,%1,%2,%3};"
        : "+f"(c[0]), "+f"(c[1]), "+f"(c[2]), "+f"(c[3])
        : "r"(a0), "r"(a1), "r"(a2), "r"(a3), "r"(b0), "r"(b1));
}

// fp16 m16n8k16, f32 accumulate. A regs = 8 halves (4x b32), B = 4 halves (2x b32).
__device__ __forceinline__ void mma_f16(float c[4],
                                        uint32_t a0, uint32_t a1,
                                        uint32_t a2, uint32_t a3,
                                        uint32_t b0, uint32_t b1) {
    asm volatile(
        "mma.sync.aligned.m16n8k16.row.col.f32.f16.f16.f32 "
        "{%0,%1,%2,%3}, {%4,%5,%6,%7}, {%8,%9}, {%0,%1,%2,%3};"
        : "+f"(c[0]), "+f"(c[1]), "+f"(c[2]), "+f"(c[3])
        : "r"(a0), "r"(a1), "r"(a2), "r"(a3), "r"(b0), "r"(b1));
}

__device__ __forceinline__ void cp16(uint32_t smem_addr, const void* gptr) {
    asm volatile("cp.async.cg.shared.global [%0], [%1], 16;"
                 :: "r"(smem_addr), "l"(gptr));
}
__device__ __forceinline__ void cp_commit() {
    asm volatile("cp.async.commit_group;");
}
template <int N>
__device__ __forceinline__ void cp_wait() {
    asm volatile("cp.async.wait_group %0;" :: "n"(N));
}

// fp16 GEMM tiling: block 64(M) x 256(N), BK=32 (= 16 b32 words/row), 4 warps
// of 64x64.  Row stride 20 words: LDS bank = (20*gid + tid) mod 32, all 32
// lanes distinct -> conflict-free fragment loads for both A and B patterns.
#define ASW 20
#define BSW 20
#define A_CH_WORDS (64 * ASW)     // 1280
#define B_CH_WORDS (256 * BSW)    // 5120
#define GEMM_SMEM_BYTES ((2 * A_CH_WORDS + 2 * B_CH_WORDS) * 4)  // 51200

// ---------------------------------------------------------------------------
// Kernel 1: bias [q][k][h] -> biasT [h][q][k]
// ---------------------------------------------------------------------------
__global__ void bias_transpose_kernel(const float* __restrict__ bias) {
    int idx = blockIdx.x * blockDim.x + threadIdx.x;
    if (idx < H_DIM * R_DIM * R_DIM) {
        int k  = idx & 255;
        int qq = (idx >> 8) & 255;
        int h  = idx >> 16;
        g_biasT[idx] = bias[((qq << 8) + k) * 8 + h];
    }
}

// ---------------------------------------------------------------------------
// Kernel 1b: fp32 -> fp16 conversion of the two activation inputs.
// ---------------------------------------------------------------------------
__global__ void f2h_kernel(const float* __restrict__ qin,
                           const float* __restrict__ kvin) {
    const float* src = blockIdx.y ? kvin : qin;
    __half* dst = blockIdx.y ? g_kvh : g_qh;
    int i = blockIdx.x * 256 + threadIdx.x;     // float4 index
    float4 v = ((const float4*)src)[i];
    __half2* d = (__half2*)(dst + i * 4);
    d[0] = __floats2half2_rn(v.x, v.y);
    d[1] = __floats2half2_rn(v.z, v.w);
}

// ---------------------------------------------------------------------------
// Kernel 1c: transpose five 256x256 weight matrices to K-major [n][k], half.
// ---------------------------------------------------------------------------
__global__ void wt_transpose_kernel(const float* __restrict__ w_q,
                                    const float* __restrict__ w_k,
                                    const float* __restrict__ w_v,
                                    const float* __restrict__ w_g,
                                    const float* __restrict__ w_o) {
    __shared__ float tile[32][33];
    int which = blockIdx.z;
    const float* W = (which == 0) ? w_q : (which == 1) ? w_k
                   : (which == 2) ? w_v : (which == 3) ? w_g : w_o;
    __half* Out = g_WTh + which * 65536;
    int bx = blockIdx.x * 32, by = blockIdx.y * 32;
    int tx = threadIdx.x, ty = threadIdx.y;   // 32 x 8
#pragma unroll
    for (int i = 0; i < 32; i += 8)
        tile[ty + i][tx] = W[(by + ty + i) * 256 + bx + tx];
    __syncthreads();
#pragma unroll
    for (int i = 0; i < 32; i += 8)
        Out[(bx + ty + i) * 256 + by + tx] = __float2half_rn(tile[tx][ty + i]);
}

// ---------------------------------------------------------------------------
// Kernel 2: fp16 m16n8k16 GEMM, cp.async double-buffered.
// type 0..3: proj (A = g_qh/g_kvh, B = WTh; epilogue norm/sigmoid; out fp32
//            [s][h][r][d]).  type 4: outproj (A = g_Oh gated, out = final+b_o).
// ---------------------------------------------------------------------------
__global__ void __launch_bounds__(128)
hgemm_kernel(const float* __restrict__ b_g,
             const float* __restrict__ b_o,
             float* __restrict__ out,
             int type_base) {
    extern __shared__ uint32_t smem[];
    uint32_t* Asm = smem;                     // 2 x [64][20]
    uint32_t* Bsm = smem + 2 * A_CH_WORDS;    // 2 x [256][20]

    int type = blockIdx.y + type_base;
    const __half* Ah = (type == 1 || type == 2) ? g_kvh
                     : (type == 4) ? g_Oh : g_qh;
    const __half* Bh = g_WTh + type * 65536;

    int t = threadIdx.x, lane = t & 31, w = t >> 5;
    int bM = blockIdx.x * 64;
    int gid = lane >> 2, tid = lane & 3;

    uint32_t asBase = (uint32_t)__cvta_generic_to_shared(Asm);
    uint32_t bsBase = (uint32_t)__cvta_generic_to_shared(Bsm);

    auto issue = [&](int kt, int buf) {
        int kc = kt * 32;
#pragma unroll
        for (int p = 0; p < 2; p++) {          // A: 64 rows x 4 cp16
            int idx = t + p * 128;
            int r = idx >> 2, c4 = idx & 3;
            const __half* src;
            if (type == 4) {
                int m = bM + r;
                int s = m >> 8, rr = m & 255;
                src = g_Oh + ((s * 8 + kt) * 256 + rr) * 32 + c4 * 8;
            } else {
                src = Ah + (bM + r) * 256 + kc + c4 * 8;
            }
            cp16(asBase + (buf * A_CH_WORDS + r * ASW + c4 * 4) * 4, src);
        }
#pragma unroll
        for (int p = 0; p < 8; p++) {          // B: 256 rows x 4 cp16
            int idx = t + p * 128;
            int r = idx >> 2, c4 = idx & 3;
            cp16(bsBase + (buf * B_CH_WORDS + r * BSW + c4 * 4) * 4,
                 Bh + r * 256 + kc + c4 * 8);
        }
        cp_commit();
    };

    float acc[4][8][4];
#pragma unroll
    for (int i = 0; i < 4; i++)
#pragma unroll
        for (int j = 0; j < 8; j++)
#pragma unroll
            for (int r = 0; r < 4; r++) acc[i][j][r] = 0.f;

    issue(0, 0);

    for (int kt = 0; kt < 8; kt++) {
        int cur = kt & 1;
        if (kt < 7) { issue(kt + 1, cur ^ 1); cp_wait<1>(); }
        else        { cp_wait<0>(); }
        __syncthreads();

        const uint32_t* As = Asm + cur * A_CH_WORDS;
        const uint32_t* Bs = Bsm + cur * B_CH_WORDS;
#pragma unroll
        for (int ks = 0; ks < 2; ks++) {       // two k16 steps per BK=32
            int kw = ks * 8;
            uint32_t af[4][4], bf[8][2];
#pragma unroll
            for (int i = 0; i < 4; i++) {
                int r0 = i * 16;
                af[i][0] = As[(r0 + gid) * ASW + kw + tid];
                af[i][1] = As[(r0 + gid + 8) * ASW + kw + tid];
                af[i][2] = As[(r0 + gid) * ASW + kw + tid + 4];
                af[i][3] = As[(r0 + gid + 8) * ASW + kw + tid + 4];
            }
#pragma unroll
            for (int j = 0; j < 8; j++) {
                int c0 = w * 64 + j * 8 + gid;
                bf[j][0] = Bs[c0 * BSW + kw + tid];
                bf[j][1] = Bs[c0 * BSW + kw + tid + 4];
            }
#pragma unroll
            for (int i = 0; i < 4; i++)
#pragma unroll
                for (int j = 0; j < 8; j++)
                    mma_f16(acc[i][j], af[i][0], af[i][1], af[i][2], af[i][3],
                            bf[j][0], bf[j][1]);
        }
        __syncthreads();
    }

    float norm = 0.17677669529663687f;  // 1/sqrt(32)
#pragma unroll
    for (int i = 0; i < 4; i++) {
#pragma unroll
        for (int j = 0; j < 8; j++) {
            int r0 = bM + i * 16 + gid;
            int c0 = w * 64 + j * 8 + tid * 2;
#pragma unroll
            for (int e = 0; e < 4; e++) {
                int row = r0 + (e >> 1) * 8;
                int col = c0 + (e & 1);
                float v = acc[i][j][e];
                if (type == 4) {
                    out[row * 256 + col] = v + b_o[col];
                } else {
                    if (type == 0) v *= norm;
                    if (type == 3) v = 1.f / (1.f + __expf(-(v + b_g[col])));
                    float* Out = (type == 0) ? g_Q : (type == 1) ? g_K
                               : (type == 2) ? g_V : g_G;
                    int s = row >> 8, rr = row & 255;
                    int h = col >> 5, d = col & 31;
                    Out[((s * 8 + h) * 256 + rr) * 32 + d] = v;
                }
            }
        }
    }
}

// ---------------------------------------------------------------------------
// Kernel 3: tensor-core attention (tf32) + fused G gating; writes g_Oh half.
// ---------------------------------------------------------------------------
#define ATTN_SMEM_WORDS (9216 + 8320 + 17408 + 256)   // Ks + Vt + Ps + Mb

__global__ void __launch_bounds__(256)
attn_mma_kernel(const float* __restrict__ bias_mask) {
    extern __shared__ uint32_t sm[];
    uint32_t* Ks = sm;                 // [256][36] tf32 K (key, d)
    uint32_t* Vt = sm + 9216;          // [32][260] tf32 V^T (d, key)
    uint32_t* Ps = sm + 17536;         // 8 warps x [32][68] tf32 P
    float*    Mb = (float*)(sm + 34944);  // [256] mask bias

    int s = blockIdx.x, h = blockIdx.y;
    int t = threadIdx.x, lane = t & 31, w = t >> 5;
    int gid = lane >> 2, tid = lane & 3;

    const float* Qg = g_Q + (s * 8 + h) * 8192;
    const float* Kg = g_K + (s * 8 + h) * 8192;
    const float* Vg = g_V + (s * 8 + h) * 8192;
    const float* Gg = g_G + (s * 8 + h) * 8192;

    uint32_t* Qs = Ps;
#pragma unroll
    for (int i = t; i < 2048; i += 256) {
        float4 v = ((const float4*)Qg)[i];
        int r = i >> 3, d = (i & 7) * 4;
        Qs[r * 36 + d + 0] = f2tf(v.x);
        Qs[r * 36 + d + 1] = f2tf(v.y);
        Qs[r * 36 + d + 2] = f2tf(v.z);
        Qs[r * 36 + d + 3] = f2tf(v.w);
    }
    __syncthreads();

    uint32_t qf[2][4][4];
#pragma unroll
    for (int i2 = 0; i2 < 2; i2++) {
        int r0 = w * 32 + i2 * 16;
#pragma unroll
        for (int ks = 0; ks < 4; ks++) {
            int kk = ks * 8;
            qf[i2][ks][0] = Qs[(r0 + gid) * 36 + kk + tid];
            qf[i2][ks][1] = Qs[(r0 + gid + 8) * 36 + kk + tid];
            qf[i2][ks][2] = Qs[(r0 + gid) * 36 + kk + tid + 4];
            qf[i2][ks][3] = Qs[(r0 + gid + 8) * 36 + kk + tid + 4];
        }
    }
    __syncthreads();

#pragma unroll
    for (int i = t; i < 2048; i += 256) {
        int r = i >> 3, d = (i & 7) * 4;
        float4 kv = ((const float4*)Kg)[i];
        Ks[r * 36 + d + 0] = f2tf(kv.x);
        Ks[r * 36 + d + 1] = f2tf(kv.y);
        Ks[r * 36 + d + 2] = f2tf(kv.z);
        Ks[r * 36 + d + 3] = f2tf(kv.w);
        float4 vv = ((const float4*)Vg)[i];
        Vt[(d + 0) * 260 + r] = f2tf(vv.x);
        Vt[(d + 1) * 260 + r] = f2tf(vv.y);
        Vt[(d + 2) * 260 + r] = f2tf(vv.z);
        Vt[(d + 3) * 260 + r] = f2tf(vv.w);
    }
    Mb[t] = (bias_mask[s * 256 + t] - 1.f) * 1e9f;
    __syncthreads();

    const float* biasBase = g_biasT + h * 65536;
    uint32_t* Pw = Ps + w * 2176;

    float oacc[2][4][4];
#pragma unroll
    for (int i2 = 0; i2 < 2; i2++)
#pragma unroll
        for (int j2 = 0; j2 < 4; j2++)
#pragma unroll
            for (int e = 0; e < 4; e++) oacc[i2][j2][e] = 0.f;
    float rs[2][2] = {{0.f, 0.f}, {0.f, 0.f}};

    for (int kc = 0; kc < 256; kc += 64) {
        float sacc[2][8][4];
#pragma unroll
        for (int i2 = 0; i2 < 2; i2++)
#pragma unroll
            for (int j = 0; j < 8; j++)
#pragma unroll
                for (int e = 0; e < 4; e++) sacc[i2][j][e] = 0.f;

#pragma unroll
        for (int ks = 0; ks < 4; ks++) {
            int kk = ks * 8;
            uint32_t bf[8][2];
#pragma unroll
            for (int j = 0; j < 8; j++) {
                int n = kc + j * 8 + gid;
                bf[j][0] = Ks[n * 36 + kk + tid];
                bf[j][1] = Ks[n * 36 + kk + tid + 4];
            }
#pragma unroll
            for (int i2 = 0; i2 < 2; i2++)
#pragma unroll
                for (int j = 0; j < 8; j++)
                    mma_tf32(sacc[i2][j], qf[i2][ks][0], qf[i2][ks][1],
                             qf[i2][ks][2], qf[i2][ks][3], bf[j][0], bf[j][1]);
        }

#pragma unroll
        for (int i2 = 0; i2 < 2; i2++) {
            int qrow = w * 32 + i2 * 16 + gid;
#pragma unroll
            for (int j = 0; j < 8; j++) {
                int col = kc + j * 8 + tid * 2;
                float2 b0 = *(const float2*)(biasBase + qrow * 256 + col);
                float2 b1 = *(const float2*)(biasBase + (qrow + 8) * 256 + col);
                float m0 = Mb[col], m1 = Mb[col + 1];
                float p0 = __expf(sacc[i2][j][0] + b0.x + m0);
                float p1 = __expf(sacc[i2][j][1] + b0.y + m1);
                float p2 = __expf(sacc[i2][j][2] + b1.x + m0);
                float p3 = __expf(sacc[i2][j][3] + b1.y + m1);
                rs[i2][0] += p0 + p1;
                rs[i2][1] += p2 + p3;
                int lr = i2 * 16 + gid, lc = j * 8 + tid * 2;
                Pw[lr * 68 + lc]           = f2tf(p0);
                Pw[lr * 68 + lc + 1]       = f2tf(p1);
                Pw[(lr + 8) * 68 + lc]     = f2tf(p2);
                Pw[(lr + 8) * 68 + lc + 1] = f2tf(p3);
            }
        }
        __syncwarp();

#pragma unroll
        for (int ks2 = 0; ks2 < 8; ks2++) {
            int kk = ks2 * 8;
            uint32_t pf[2][4];
#pragma unroll
            for (int i2 = 0; i2 < 2; i2++) {
                int lr = i2 * 16 + gid;
                pf[i2][0] = Pw[lr * 68 + kk + tid];
                pf[i2][1] = Pw[(lr + 8) * 68 + kk + tid];
                pf[i2][2] = Pw[lr * 68 + kk + tid + 4];
                pf[i2][3] = Pw[(lr + 8) * 68 + kk + tid + 4];
            }
            uint32_t vf[4][2];
#pragma unroll
            for (int j2 = 0; j2 < 4; j2++) {
                int d = j2 * 8 + gid;
                vf[j2][0] = Vt[d * 260 + kc + kk + tid];
                vf[j2][1] = Vt[d * 260 + kc + kk + tid + 4];
            }
#pragma unroll
            for (int i2 = 0; i2 < 2; i2++)
#pragma unroll
                for (int j2 = 0; j2 < 4; j2++)
                    mma_tf32(oacc[i2][j2], pf[i2][0], pf[i2][1],
                             pf[i2][2], pf[i2][3], vf[j2][0], vf[j2][1]);
        }
        __syncwarp();
    }

#pragma unroll
    for (int i2 = 0; i2 < 2; i2++)
#pragma unroll
        for (int rp = 0; rp < 2; rp++) {
            float v = rs[i2][rp];
            v += __shfl_xor_sync(0xffffffffu, v, 1);
            v += __shfl_xor_sync(0xffffffffu, v, 2);
            rs[i2][rp] = 1.f / v;
        }

    // normalize, gate with G, write g_Oh = half(O * G)
    __half* Og = g_Oh + (s * 8 + h) * 8192;
#pragma unroll
    for (int i2 = 0; i2 < 2; i2++) {
        int r0 = w * 32 + i2 * 16 + gid;
#pragma unroll
        for (int j2 = 0; j2 < 4; j2++) {
            int c = j2 * 8 + tid * 2;
            float2 gv0 = *(const float2*)(Gg + r0 * 32 + c);
            float2 gv1 = *(const float2*)(Gg + (r0 + 8) * 32 + c);
            ((__half2*)(Og + r0 * 32 + c))[0] = __floats2half2_rn(
                oacc[i2][j2][0] * rs[i2][0] * gv0.x,
                oacc[i2][j2][1] * rs[i2][0] * gv0.y);
            ((__half2*)(Og + (r0 + 8) * 32 + c))[0] = __floats2half2_rn(
                oacc[i2][j2][2] * rs[i2][1] * gv1.x,
                oacc[i2][j2][3] * rs[i2][1] * gv1.y);
        }
    }
}

// ---------------------------------------------------------------------------
extern "C" void kernel_launch(void* const* d_in, const int* in_sizes, int n_in,
                              void* d_out, int out_size) {
    const float* q    = (const float*)d_in[0];
    const float* kv   = (const float*)d_in[1];
    const float* bias = (const float*)d_in[2];
    const float* mask = (const float*)d_in[3];
    const float* w_q  = (const float*)d_in[4];
    const float* w_k  = (const float*)d_in[5];
    const float* w_v  = (const float*)d_in[6];
    const float* w_g  = (const float*)d_in[7];
    const float* b_g  = (const float*)d_in[8];
    const float* w_o  = (const float*)d_in[9];
    const float* b_o  = (const float*)d_in[10];
    float* out = (float*)d_out;

    bias_transpose_kernel<<<(H_DIM * R_DIM * R_DIM + 255) / 256, 256>>>(bias);
    f2h_kernel<<<dim3(8192, 2), 256>>>(q, kv);
    wt_transpose_kernel<<<dim3(8, 8, 5), dim3(32, 8)>>>(w_q, w_k, w_v, w_g, w_o);

    cudaFuncSetAttribute(hgemm_kernel,
                         cudaFuncAttributeMaxDynamicSharedMemorySize,
                         GEMM_SMEM_BYTES);
    // projections: types 0..3
    hgemm_kernel<<<dim3(SR_DIM / 64, 4), 128, GEMM_SMEM_BYTES>>>(
        b_g, b_o, out, 0);

    const int ATTN_SMEM = ATTN_SMEM_WORDS * 4;   // 140800 B
    cudaFuncSetAttribute(attn_mma_kernel,
                         cudaFuncAttributeMaxDynamicSharedMemorySize, ATTN_SMEM);
    attn_mma_kernel<<<dim3(S_DIM, H_DIM), 256, ATTN_SMEM>>>(mask);

    // output projection: type 4
    hgemm_kernel<<<dim3(SR_DIM / 64, 1), 128, GEMM_SMEM_BYTES>>>(
        b_g, b_o, out, 4);
}

// round 11
// speedup vs baseline: 1.1618x; 1.1618x over previous
#include <cuda_runtime.h>
#include <cuda_fp16.h>
#include <math.h>
#include <stdint.h>

#define S_DIM 128
#define R_DIM 256
#define C_DIM 256
#define H_DIM 8
#define D_DIM 32
#define HD_DIM 256
#define SR_DIM (S_DIM * R_DIM)

// Scratch (device globals; allocation-free contract)
__device__ float  g_biasT[H_DIM * R_DIM * R_DIM];        // [h][q][k]
__device__ __half g_qh[SR_DIM * 256];                    // q input, half
__device__ __half g_kvh[SR_DIM * 256];                   // kv input, half
__device__ __half g_Qh[S_DIM * H_DIM * R_DIM * D_DIM];   // [s][h][r][d]
__device__ __half g_Kh[S_DIM * H_DIM * R_DIM * D_DIM];
__device__ __half g_Vh[S_DIM * H_DIM * R_DIM * D_DIM];
__device__ __half g_Gh[S_DIM * H_DIM * R_DIM * D_DIM];
__device__ __half g_Oh[S_DIM * H_DIM * R_DIM * D_DIM];   // gated O
__device__ __half g_WTh[5 * 256 * 256];                  // weights [n][k], half

// ---------------------------------------------------------------------------
// helpers
// ---------------------------------------------------------------------------
__device__ __forceinline__ uint32_t f2tf(float f) {
    uint32_t u;
    asm("cvt.rna.tf32.f32 %0, %1;" : "=r"(u) : "f"(f));
    return u;
}

__device__ __forceinline__ void mma_tf32(float c[4],
                                         uint32_t a0, uint32_t a1,
                                         uint32_t a2, uint32_t a3,
                                         uint32_t b0, uint32_t b1) {
    asm volatile(
        "mma.sync.aligned.m16n8k8.row.col.f32.tf32.tf32.f32 "
        "{%0,%1,%2,%3}, {%4,%5,%6,%7}, {%8,%9}, {%0,%1,%2,%3};"
        : "+f"(c[0]), "+f"(c[1]), "+f"(c[2]), "+f"(c[3])
        : "r"(a0), "r"(a1), "r"(a2), "r"(a3), "r"(b0), "r"(b1));
}

__device__ __forceinline__ void mma_f16(float c[4],
                                        uint32_t a0, uint32_t a1,
                                        uint32_t a2, uint32_t a3,
                                        uint32_t b0, uint32_t b1) {
    asm volatile(
        "mma.sync.aligned.m16n8k16.row.col.f32.f16.f16.f32 "
        "{%0,%1,%2,%3}, {%4,%5,%6,%7}, {%8,%9}, {%0,%1,%2,%3};"
        : "+f"(c[0]), "+f"(c[1]), "+f"(c[2]), "+f"(c[3])
        : "r"(a0), "r"(a1), "r"(a2), "r"(a3), "r"(b0), "r"(b1));
}

__device__ __forceinline__ void cp16(uint32_t smem_addr, const void* gptr) {
    asm volatile("cp.async.cg.shared.global [%0], [%1], 16;"
                 :: "r"(smem_addr), "l"(gptr));
}
__device__ __forceinline__ void cp_commit() {
    asm volatile("cp.async.commit_group;");
}
template <int N>
__device__ __forceinline__ void cp_wait() {
    asm volatile("cp.async.wait_group %0;" :: "n"(N));
}

// fp16 GEMM tiling: block 64(M) x 256(N), BK=32 (16 b32 words/row), 4 warps
// of 64x64.  Row stride 20 words -> conflict-free fragment LDS.
// 4-stage cp.async pipeline.
#define ASW 20
#define BSW 20
#define A_CH_WORDS (64 * ASW)     // 1280
#define B_CH_WORDS (256 * BSW)    // 5120
#define NSTAGE 4
#define GEMM_SMEM_BYTES (NSTAGE * (A_CH_WORDS + B_CH_WORDS) * 4)  // 102400

// ---------------------------------------------------------------------------
// Kernel 1: bias [q][k][h] -> biasT [h][q][k]
// ---------------------------------------------------------------------------
__global__ void bias_transpose_kernel(const float* __restrict__ bias) {
    int idx = blockIdx.x * blockDim.x + threadIdx.x;
    if (idx < H_DIM * R_DIM * R_DIM) {
        int k  = idx & 255;
        int qq = (idx >> 8) & 255;
        int h  = idx >> 16;
        g_biasT[idx] = bias[((qq << 8) + k) * 8 + h];
    }
}

// ---------------------------------------------------------------------------
// Kernel 1b: fp32 -> fp16 conversion of the two activation inputs.
// ---------------------------------------------------------------------------
__global__ void f2h_kernel(const float* __restrict__ qin,
                           const float* __restrict__ kvin) {
    const float* src = blockIdx.y ? kvin : qin;
    __half* dst = blockIdx.y ? g_kvh : g_qh;
    int i = blockIdx.x * 256 + threadIdx.x;     // float4 index
    float4 v = ((const float4*)src)[i];
    __half2* d = (__half2*)(dst + i * 4);
    d[0] = __floats2half2_rn(v.x, v.y);
    d[1] = __floats2half2_rn(v.z, v.w);
}

// ---------------------------------------------------------------------------
// Kernel 1c: transpose five 256x256 weight matrices to K-major [n][k], half.
// ---------------------------------------------------------------------------
__global__ void wt_transpose_kernel(const float* __restrict__ w_q,
                                    const float* __restrict__ w_k,
                                    const float* __restrict__ w_v,
                                    const float* __restrict__ w_g,
                                    const float* __restrict__ w_o) {
    __shared__ float tile[32][33];
    int which = blockIdx.z;
    const float* W = (which == 0) ? w_q : (which == 1) ? w_k
                   : (which == 2) ? w_v : (which == 3) ? w_g : w_o;
    __half* Out = g_WTh + which * 65536;
    int bx = blockIdx.x * 32, by = blockIdx.y * 32;
    int tx = threadIdx.x, ty = threadIdx.y;   // 32 x 8
#pragma unroll
    for (int i = 0; i < 32; i += 8)
        tile[ty + i][tx] = W[(by + ty + i) * 256 + bx + tx];
    __syncthreads();
#pragma unroll
    for (int i = 0; i < 32; i += 8)
        Out[(bx + ty + i) * 256 + by + tx] = __float2half_rn(tile[tx][ty + i]);
}

// ---------------------------------------------------------------------------
// Kernel 2: fp16 m16n8k16 GEMM, 4-stage cp.async pipeline.
// type 0..3: proj (epilogue norm/sigmoid; half outputs [s][h][r][d]).
// type 4: outproj (A = g_Oh; out = final fp32 + b_o).
// ---------------------------------------------------------------------------
__global__ void __launch_bounds__(128)
hgemm_kernel(const float* __restrict__ b_g,
             const float* __restrict__ b_o,
             float* __restrict__ out,
             int type_base) {
    extern __shared__ uint32_t smem[];
    uint32_t* Asm = smem;                         // NSTAGE x [64][20]
    uint32_t* Bsm = smem + NSTAGE * A_CH_WORDS;   // NSTAGE x [256][20]

    int type = blockIdx.y + type_base;
    const __half* Ah = (type == 1 || type == 2) ? g_kvh
                     : (type == 4) ? g_Oh : g_qh;
    const __half* Bh = g_WTh + type * 65536;

    int t = threadIdx.x, lane = t & 31, w = t >> 5;
    int bM = blockIdx.x * 64;
    int gid = lane >> 2, tid = lane & 3;

    uint32_t asBase = (uint32_t)__cvta_generic_to_shared(Asm);
    uint32_t bsBase = (uint32_t)__cvta_generic_to_shared(Bsm);

    auto issue = [&](int kt, int buf) {
        int kc = kt * 32;
#pragma unroll
        for (int p = 0; p < 2; p++) {          // A: 64 rows x 4 cp16
            int idx = t + p * 128;
            int r = idx >> 2, c4 = idx & 3;
            const __half* src;
            if (type == 4) {
                int m = bM + r;
                int s = m >> 8, rr = m & 255;
                src = g_Oh + ((s * 8 + kt) * 256 + rr) * 32 + c4 * 8;
            } else {
                src = Ah + (bM + r) * 256 + kc + c4 * 8;
            }
            cp16(asBase + (buf * A_CH_WORDS + r * ASW + c4 * 4) * 4, src);
        }
#pragma unroll
        for (int p = 0; p < 8; p++) {          // B: 256 rows x 4 cp16
            int idx = t + p * 128;
            int r = idx >> 2, c4 = idx & 3;
            cp16(bsBase + (buf * B_CH_WORDS + r * BSW + c4 * 4) * 4,
                 Bh + r * 256 + kc + c4 * 8);
        }
        cp_commit();
    };

    float acc[4][8][4];
#pragma unroll
    for (int i = 0; i < 4; i++)
#pragma unroll
        for (int j = 0; j < 8; j++)
#pragma unroll
            for (int r = 0; r < 4; r++) acc[i][j][r] = 0.f;

    issue(0, 0);
    issue(1, 1);
    issue(2, 2);

    for (int kt = 0; kt < 8; kt++) {
        int cur = kt & 3;
        // keep 3 chunks in flight; exact tail waits
        if (kt < 5)      { issue(kt + 3, (kt + 3) & 3); cp_wait<3>(); }
        else if (kt == 5) cp_wait<2>();
        else if (kt == 6) cp_wait<1>();
        else              cp_wait<0>();
        __syncthreads();

        const uint32_t* As = Asm + cur * A_CH_WORDS;
        const uint32_t* Bs = Bsm + cur * B_CH_WORDS;
#pragma unroll
        for (int ks = 0; ks < 2; ks++) {       // two k16 steps per BK=32
            int kw = ks * 8;
            uint32_t af[4][4], bf[8][2];
#pragma unroll
            for (int i = 0; i < 4; i++) {
                int r0 = i * 16;
                af[i][0] = As[(r0 + gid) * ASW + kw + tid];
                af[i][1] = As[(r0 + gid + 8) * ASW + kw + tid];
                af[i][2] = As[(r0 + gid) * ASW + kw + tid + 4];
                af[i][3] = As[(r0 + gid + 8) * ASW + kw + tid + 4];
            }
#pragma unroll
            for (int j = 0; j < 8; j++) {
                int c0 = w * 64 + j * 8 + gid;
                bf[j][0] = Bs[c0 * BSW + kw + tid];
                bf[j][1] = Bs[c0 * BSW + kw + tid + 4];
            }
#pragma unroll
            for (int i = 0; i < 4; i++)
#pragma unroll
                for (int j = 0; j < 8; j++)
                    mma_f16(acc[i][j], af[i][0], af[i][1], af[i][2], af[i][3],
                            bf[j][0], bf[j][1]);
        }
        __syncthreads();
    }

    float norm = 0.17677669529663687f;  // 1/sqrt(32)
#pragma unroll
    for (int i = 0; i < 4; i++) {
#pragma unroll
        for (int j = 0; j < 8; j++) {
            int r0 = bM + i * 16 + gid;
            int c0 = w * 64 + j * 8 + tid * 2;
#pragma unroll
            for (int e2 = 0; e2 < 2; e2++) {   // row pair: r0, r0+8
                int row = r0 + e2 * 8;
                float v0 = acc[i][j][e2 * 2 + 0];
                float v1 = acc[i][j][e2 * 2 + 1];
                if (type == 4) {
                    out[row * 256 + c0]     = v0 + b_o[c0];
                    out[row * 256 + c0 + 1] = v1 + b_o[c0 + 1];
                } else {
                    if (type == 0) { v0 *= norm; v1 *= norm; }
                    if (type == 3) {
                        v0 = 1.f / (1.f + __expf(-(v0 + b_g[c0])));
                        v1 = 1.f / (1.f + __expf(-(v1 + b_g[c0 + 1])));
                    }
                    __half* Out = (type == 0) ? g_Qh : (type == 1) ? g_Kh
                                : (type == 2) ? g_Vh : g_Gh;
                    int s = row >> 8, rr = row & 255;
                    int h = c0 >> 5, d = c0 & 31;
                    *(__half2*)(Out + ((s * 8 + h) * 256 + rr) * 32 + d) =
                        __floats2half2_rn(v0, v1);
                }
            }
        }
    }
}

// ---------------------------------------------------------------------------
// Kernel 3: tensor-core attention (tf32) reading half Q/K/V/G; gated half out.
// ---------------------------------------------------------------------------
#define ATTN_SMEM_WORDS (9216 + 8320 + 17408 + 256)   // Ks + Vt + Ps + Mb

__global__ void __launch_bounds__(256)
attn_mma_kernel(const float* __restrict__ bias_mask) {
    extern __shared__ uint32_t sm[];
    uint32_t* Ks = sm;                 // [256][36] tf32 K (key, d)
    uint32_t* Vt = sm + 9216;          // [32][260] tf32 V^T (d, key)
    uint32_t* Ps = sm + 17536;         // 8 warps x [32][68] tf32 P
    float*    Mb = (float*)(sm + 34944);  // [256] mask bias

    int s = blockIdx.x, h = blockIdx.y;
    int t = threadIdx.x, lane = t & 31, w = t >> 5;
    int gid = lane >> 2, tid = lane & 3;

    const __half* Qg = g_Qh + (s * 8 + h) * 8192;
    const __half* Kg = g_Kh + (s * 8 + h) * 8192;
    const __half* Vg = g_Vh + (s * 8 + h) * 8192;
    const __half* Gg = g_Gh + (s * 8 + h) * 8192;

    // ---- stage Q (half -> tf32) into Ps region temporarily: Qs[256][36]
    uint32_t* Qs = Ps;
#pragma unroll
    for (int i = t; i < 1024; i += 256) {       // 1024 x 16B = 8192 halves
        uint4 raw = ((const uint4*)Qg)[i];
        int r = i >> 2, d = (i & 3) * 8;
        const __half2* hp = (const __half2*)&raw;
#pragma unroll
        for (int e = 0; e < 4; e++) {
            float2 f = __half22float2(hp[e]);
            Qs[r * 36 + d + e * 2 + 0] = f2tf(f.x);
            Qs[r * 36 + d + e * 2 + 1] = f2tf(f.y);
        }
    }
    __syncthreads();

    uint32_t qf[2][4][4];
#pragma unroll
    for (int i2 = 0; i2 < 2; i2++) {
        int r0 = w * 32 + i2 * 16;
#pragma unroll
        for (int ks = 0; ks < 4; ks++) {
            int kk = ks * 8;
            qf[i2][ks][0] = Qs[(r0 + gid) * 36 + kk + tid];
            qf[i2][ks][1] = Qs[(r0 + gid + 8) * 36 + kk + tid];
            qf[i2][ks][2] = Qs[(r0 + gid) * 36 + kk + tid + 4];
            qf[i2][ks][3] = Qs[(r0 + gid + 8) * 36 + kk + tid + 4];
        }
    }
    __syncthreads();

    // ---- stage K and V^T (half -> tf32)
#pragma unroll
    for (int i = t; i < 1024; i += 256) {
        int r = i >> 2, d = (i & 3) * 8;
        uint4 kraw = ((const uint4*)Kg)[i];
        const __half2* kp = (const __half2*)&kraw;
#pragma unroll
        for (int e = 0; e < 4; e++) {
            float2 f = __half22float2(kp[e]);
            Ks[r * 36 + d + e * 2 + 0] = f2tf(f.x);
            Ks[r * 36 + d + e * 2 + 1] = f2tf(f.y);
        }
        uint4 vraw = ((const uint4*)Vg)[i];
        const __half2* vp = (const __half2*)&vraw;
#pragma unroll
        for (int e = 0; e < 4; e++) {
            float2 f = __half22float2(vp[e]);
            Vt[(d + e * 2 + 0) * 260 + r] = f2tf(f.x);
            Vt[(d + e * 2 + 1) * 260 + r] = f2tf(f.y);
        }
    }
    Mb[t] = (bias_mask[s * 256 + t] - 1.f) * 1e9f;
    __syncthreads();

    const float* biasBase = g_biasT + h * 65536;
    uint32_t* Pw = Ps + w * 2176;   // per-warp private P tile [32][68]

    float oacc[2][4][4];
#pragma unroll
    for (int i2 = 0; i2 < 2; i2++)
#pragma unroll
        for (int j2 = 0; j2 < 4; j2++)
#pragma unroll
            for (int e = 0; e < 4; e++) oacc[i2][j2][e] = 0.f;
    float rs[2][2] = {{0.f, 0.f}, {0.f, 0.f}};

    for (int kc = 0; kc < 256; kc += 64) {
        float sacc[2][8][4];
#pragma unroll
        for (int i2 = 0; i2 < 2; i2++)
#pragma unroll
            for (int j = 0; j < 8; j++)
#pragma unroll
                for (int e = 0; e < 4; e++) sacc[i2][j][e] = 0.f;

#pragma unroll
        for (int ks = 0; ks < 4; ks++) {
            int kk = ks * 8;
            uint32_t bf[8][2];
#pragma unroll
            for (int j = 0; j < 8; j++) {
                int n = kc + j * 8 + gid;
                bf[j][0] = Ks[n * 36 + kk + tid];
                bf[j][1] = Ks[n * 36 + kk + tid + 4];
            }
#pragma unroll
            for (int i2 = 0; i2 < 2; i2++)
#pragma unroll
                for (int j = 0; j < 8; j++)
                    mma_tf32(sacc[i2][j], qf[i2][ks][0], qf[i2][ks][1],
                             qf[i2][ks][2], qf[i2][ks][3], bf[j][0], bf[j][1]);
        }

#pragma unroll
        for (int i2 = 0; i2 < 2; i2++) {
            int qrow = w * 32 + i2 * 16 + gid;
#pragma unroll
            for (int j = 0; j < 8; j++) {
                int col = kc + j * 8 + tid * 2;
                float2 b0 = *(const float2*)(biasBase + qrow * 256 + col);
                float2 b1 = *(const float2*)(biasBase + (qrow + 8) * 256 + col);
                float m0 = Mb[col], m1 = Mb[col + 1];
                float p0 = __expf(sacc[i2][j][0] + b0.x + m0);
                float p1 = __expf(sacc[i2][j][1] + b0.y + m1);
                float p2 = __expf(sacc[i2][j][2] + b1.x + m0);
                float p3 = __expf(sacc[i2][j][3] + b1.y + m1);
                rs[i2][0] += p0 + p1;
                rs[i2][1] += p2 + p3;
                int lr = i2 * 16 + gid, lc = j * 8 + tid * 2;
                Pw[lr * 68 + lc]           = f2tf(p0);
                Pw[lr * 68 + lc + 1]       = f2tf(p1);
                Pw[(lr + 8) * 68 + lc]     = f2tf(p2);
                Pw[(lr + 8) * 68 + lc + 1] = f2tf(p3);
            }
        }
        __syncwarp();

#pragma unroll
        for (int ks2 = 0; ks2 < 8; ks2++) {
            int kk = ks2 * 8;
            uint32_t pf[2][4];
#pragma unroll
            for (int i2 = 0; i2 < 2; i2++) {
                int lr = i2 * 16 + gid;
                pf[i2][0] = Pw[lr * 68 + kk + tid];
                pf[i2][1] = Pw[(lr + 8) * 68 + kk + tid];
                pf[i2][2] = Pw[lr * 68 + kk + tid + 4];
                pf[i2][3] = Pw[(lr + 8) * 68 + kk + tid + 4];
            }
            uint32_t vf[4][2];
#pragma unroll
            for (int j2 = 0; j2 < 4; j2++) {
                int d = j2 * 8 + gid;
                vf[j2][0] = Vt[d * 260 + kc + kk + tid];
                vf[j2][1] = Vt[d * 260 + kc + kk + tid + 4];
            }
#pragma unroll
            for (int i2 = 0; i2 < 2; i2++)
#pragma unroll
                for (int j2 = 0; j2 < 4; j2++)
                    mma_tf32(oacc[i2][j2], pf[i2][0], pf[i2][1],
                             pf[i2][2], pf[i2][3], vf[j2][0], vf[j2][1]);
        }
        __syncwarp();
    }

#pragma unroll
    for (int i2 = 0; i2 < 2; i2++)
#pragma unroll
        for (int rp = 0; rp < 2; rp++) {
            float v = rs[i2][rp];
            v += __shfl_xor_sync(0xffffffffu, v, 1);
            v += __shfl_xor_sync(0xffffffffu, v, 2);
            rs[i2][rp] = 1.f / v;
        }

    // normalize, gate with G, write g_Oh = half(O * G)
    __half* Og = g_Oh + (s * 8 + h) * 8192;
#pragma unroll
    for (int i2 = 0; i2 < 2; i2++) {
        int r0 = w * 32 + i2 * 16 + gid;
#pragma unroll
        for (int j2 = 0; j2 < 4; j2++) {
            int c = j2 * 8 + tid * 2;
            float2 gv0 = __half22float2(*(const __half2*)(Gg + r0 * 32 + c));
            float2 gv1 = __half22float2(*(const __half2*)(Gg + (r0 + 8) * 32 + c));
            ((__half2*)(Og + r0 * 32 + c))[0] = __floats2half2_rn(
                oacc[i2][j2][0] * rs[i2][0] * gv0.x,
                oacc[i2][j2][1] * rs[i2][0] * gv0.y);
            ((__half2*)(Og + (r0 + 8) * 32 + c))[0] = __floats2half2_rn(
                oacc[i2][j2][2] * rs[i2][1] * gv1.x,
                oacc[i2][j2][3] * rs[i2][1] * gv1.y);
        }
    }
}

// ---------------------------------------------------------------------------
extern "C" void kernel_launch(void* const* d_in, const int* in_sizes, int n_in,
                              void* d_out, int out_size) {
    const float* q    = (const float*)d_in[0];
    const float* kv   = (const float*)d_in[1];
    const float* bias = (const float*)d_in[2];
    const float* mask = (const float*)d_in[3];
    const float* w_q  = (const float*)d_in[4];
    const float* w_k  = (const float*)d_in[5];
    const float* w_v  = (const float*)d_in[6];
    const float* w_g  = (const float*)d_in[7];
    const float* b_g  = (const float*)d_in[8];
    const float* w_o  = (const float*)d_in[9];
    const float* b_o  = (const float*)d_in[10];
    float* out = (float*)d_out;

    bias_transpose_kernel<<<(H_DIM * R_DIM * R_DIM + 255) / 256, 256>>>(bias);
    f2h_kernel<<<dim3(8192, 2), 256>>>(q, kv);
    wt_transpose_kernel<<<dim3(8, 8, 5), dim3(32, 8)>>>(w_q, w_k, w_v, w_g, w_o);

    cudaFuncSetAttribute(hgemm_kernel,
                         cudaFuncAttributeMaxDynamicSharedMemorySize,
                         GEMM_SMEM_BYTES);
    // projections: types 0..3
    hgemm_kernel<<<dim3(SR_DIM / 64, 4), 128, GEMM_SMEM_BYTES>>>(
        b_g, b_o, out, 0);

    const int ATTN_SMEM = ATTN_SMEM_WORDS * 4;   // 140800 B
    cudaFuncSetAttribute(attn_mma_kernel,
                         cudaFuncAttributeMaxDynamicSharedMemorySize, ATTN_SMEM);
    attn_mma_kernel<<<dim3(S_DIM, H_DIM), 256, ATTN_SMEM>>>(mask);

    // output projection: type 4
    hgemm_kernel<<<dim3(SR_DIM / 64, 1), 128, GEMM_SMEM_BYTES>>>(
        b_g, b_o, out, 4);
}

// round 12
// speedup vs baseline: 1.1978x; 1.0310x over previous
#include <cuda_runtime.h>
#include <cuda_fp16.h>
#include <math.h>
#include <stdint.h>

#define S_DIM 128
#define R_DIM 256
#define C_DIM 256
#define H_DIM 8
#define D_DIM 32
#define HD_DIM 256
#define SR_DIM (S_DIM * R_DIM)

// Scratch (device globals; allocation-free contract)
__device__ float  g_biasT[H_DIM * R_DIM * R_DIM];        // [h][q][k]
__device__ __half g_qh[SR_DIM * 256];                    // q input, half
__device__ __half g_kvh[SR_DIM * 256];                   // kv input, half
__device__ __half g_Qh[S_DIM * H_DIM * R_DIM * D_DIM];   // [s][h][r][d]
__device__ __half g_Kh[S_DIM * H_DIM * R_DIM * D_DIM];
__device__ __half g_Vh[S_DIM * H_DIM * R_DIM * D_DIM];
__device__ __half g_Gh[S_DIM * H_DIM * R_DIM * D_DIM];
__device__ __half g_Oh[S_DIM * H_DIM * R_DIM * D_DIM];   // gated O
__device__ __half g_WTh[5 * 256 * 256];                  // weights [n][k], half

// ---------------------------------------------------------------------------
// helpers
// ---------------------------------------------------------------------------
__device__ __forceinline__ uint32_t f2tf(float f) {
    uint32_t u;
    asm("cvt.rna.tf32.f32 %0, %1;" : "=r"(u) : "f"(f));
    return u;
}

__device__ __forceinline__ void mma_tf32(float c[4],
                                         uint32_t a0, uint32_t a1,
                                         uint32_t a2, uint32_t a3,
                                         uint32_t b0, uint32_t b1) {
    asm volatile(
        "mma.sync.aligned.m16n8k8.row.col.f32.tf32.tf32.f32 "
        "{%0,%1,%2,%3}, {%4,%5,%6,%7}, {%8,%9}, {%0,%1,%2,%3};"
        : "+f"(c[0]), "+f"(c[1]), "+f"(c[2]), "+f"(c[3])
        : "r"(a0), "r"(a1), "r"(a2), "r"(a3), "r"(b0), "r"(b1));
}

__device__ __forceinline__ void mma_f16(float c[4],
                                        uint32_t a0, uint32_t a1,
                                        uint32_t a2, uint32_t a3,
                                        uint32_t b0, uint32_t b1) {
    asm volatile(
        "mma.sync.aligned.m16n8k16.row.col.f32.f16.f16.f32 "
        "{%0,%1,%2,%3}, {%4,%5,%6,%7}, {%8,%9}, {%0,%1,%2,%3};"
        : "+f"(c[0]), "+f"(c[1]), "+f"(c[2]), "+f"(c[3])
        : "r"(a0), "r"(a1), "r"(a2), "r"(a3), "r"(b0), "r"(b1));
}

__device__ __forceinline__ void cp16(uint32_t smem_addr, const void* gptr) {
    asm volatile("cp.async.cg.shared.global [%0], [%1], 16;"
                 :: "r"(smem_addr), "l"(gptr));
}
__device__ __forceinline__ void cp_commit() {
    asm volatile("cp.async.commit_group;");
}
template <int N>
__device__ __forceinline__ void cp_wait() {
    asm volatile("cp.async.wait_group %0;" :: "n"(N));
}

// fp16 GEMM tiling: block 128(M) x 256(N), BK=64, 8 warps (2M x 4N) of 64x64.
// Row = 64 halves = 32 b32 words, padded stride 36 -> conflict-free frag LDS
// (A: bank 4*gid+tid; B: 288j wraps to 0 mod 32).
// 2-stage cp.async pipeline, 4 K-chunks.
#define ROWW 36
#define A_CH_WORDS (128 * ROWW)   // 4608
#define B_CH_WORDS (256 * ROWW)   // 9216
#define GEMM_SMEM_BYTES (2 * (A_CH_WORDS + B_CH_WORDS) * 4)  // 110592

// ---------------------------------------------------------------------------
// Kernel 1: bias [q][k][h] -> biasT [h][q][k]
// ---------------------------------------------------------------------------
__global__ void bias_transpose_kernel(const float* __restrict__ bias) {
    int idx = blockIdx.x * blockDim.x + threadIdx.x;
    if (idx < H_DIM * R_DIM * R_DIM) {
        int k  = idx & 255;
        int qq = (idx >> 8) & 255;
        int h  = idx >> 16;
        g_biasT[idx] = bias[((qq << 8) + k) * 8 + h];
    }
}

// ---------------------------------------------------------------------------
// Kernel 1b: fp32 -> fp16 conversion of the two activation inputs.
// ---------------------------------------------------------------------------
__global__ void f2h_kernel(const float* __restrict__ qin,
                           const float* __restrict__ kvin) {
    const float* src = blockIdx.y ? kvin : qin;
    __half* dst = blockIdx.y ? g_kvh : g_qh;
    int i = blockIdx.x * 256 + threadIdx.x;     // float4 index
    float4 v = ((const float4*)src)[i];
    __half2* d = (__half2*)(dst + i * 4);
    d[0] = __floats2half2_rn(v.x, v.y);
    d[1] = __floats2half2_rn(v.z, v.w);
}

// ---------------------------------------------------------------------------
// Kernel 1c: transpose five 256x256 weight matrices to K-major [n][k], half.
// ---------------------------------------------------------------------------
__global__ void wt_transpose_kernel(const float* __restrict__ w_q,
                                    const float* __restrict__ w_k,
                                    const float* __restrict__ w_v,
                                    const float* __restrict__ w_g,
                                    const float* __restrict__ w_o) {
    __shared__ float tile[32][33];
    int which = blockIdx.z;
    const float* W = (which == 0) ? w_q : (which == 1) ? w_k
                   : (which == 2) ? w_v : (which == 3) ? w_g : w_o;
    __half* Out = g_WTh + which * 65536;
    int bx = blockIdx.x * 32, by = blockIdx.y * 32;
    int tx = threadIdx.x, ty = threadIdx.y;   // 32 x 8
#pragma unroll
    for (int i = 0; i < 32; i += 8)
        tile[ty + i][tx] = W[(by + ty + i) * 256 + bx + tx];
    __syncthreads();
#pragma unroll
    for (int i = 0; i < 32; i += 8)
        Out[(bx + ty + i) * 256 + by + tx] = __float2half_rn(tile[tx][ty + i]);
}

// ---------------------------------------------------------------------------
// Kernel 2: fp16 m16n8k16 GEMM, block 128x256, BK=64, 2-stage pipeline.
// type 0..3: proj (epilogue norm/sigmoid; half outputs [s][h][r][d]).
// type 4: outproj (A = g_Oh; out = final fp32 + b_o).
// ---------------------------------------------------------------------------
__global__ void __launch_bounds__(256)
hgemm_kernel(const float* __restrict__ b_g,
             const float* __restrict__ b_o,
             float* __restrict__ out,
             int type_base) {
    extern __shared__ uint32_t smem[];
    uint32_t* Asm = smem;                      // 2 x [128][36]
    uint32_t* Bsm = smem + 2 * A_CH_WORDS;     // 2 x [256][36]

    int type = blockIdx.y + type_base;
    const __half* Ah = (type == 1 || type == 2) ? g_kvh
                     : (type == 4) ? g_Oh : g_qh;
    const __half* Bh = g_WTh + type * 65536;

    int t = threadIdx.x, lane = t & 31, w = t >> 5;
    int warpM = w >> 2, warpN = w & 3;         // 2 x 4 warp grid
    int bM = blockIdx.x * 128;
    int gid = lane >> 2, tid = lane & 3;

    uint32_t asBase = (uint32_t)__cvta_generic_to_shared(Asm);
    uint32_t bsBase = (uint32_t)__cvta_generic_to_shared(Bsm);

    auto issue = [&](int kt, int buf) {
        int kc = kt * 64;
#pragma unroll
        for (int p = 0; p < 4; p++) {          // A: 128 rows x 8 cp16
            int idx = t + p * 256;
            int r = idx >> 3, c4 = idx & 7;    // c4*8 halves within 64-col row
            const __half* src;
            if (type == 4) {
                int m = bM + r;
                int s = m >> 8, rr = m & 255;
                int head = (kc >> 5) + (c4 >> 2);
                int d0 = (c4 & 3) * 8;
                src = g_Oh + ((s * 8 + head) * 256 + rr) * 32 + d0;
            } else {
                src = Ah + (bM + r) * 256 + kc + c4 * 8;
            }
            cp16(asBase + (buf * A_CH_WORDS + r * ROWW + c4 * 4) * 4, src);
        }
#pragma unroll
        for (int p = 0; p < 8; p++) {          // B: 256 rows x 8 cp16
            int idx = t + p * 256;
            int r = idx >> 3, c4 = idx & 7;
            cp16(bsBase + (buf * B_CH_WORDS + r * ROWW + c4 * 4) * 4,
                 Bh + r * 256 + kc + c4 * 8);
        }
        cp_commit();
    };

    float acc[4][8][4];
#pragma unroll
    for (int i = 0; i < 4; i++)
#pragma unroll
        for (int j = 0; j < 8; j++)
#pragma unroll
            for (int r = 0; r < 4; r++) acc[i][j][r] = 0.f;

    issue(0, 0);

    for (int kt = 0; kt < 4; kt++) {
        int cur = kt & 1;
        __syncthreads();                       // all warps done with buf cur
        if (kt < 3) { issue(kt + 1, cur ^ 1); cp_wait<1>(); }
        else        { cp_wait<0>(); }
        __syncthreads();                       // buf cur data visible

        const uint32_t* As = Asm + cur * A_CH_WORDS;
        const uint32_t* Bs = Bsm + cur * B_CH_WORDS;
#pragma unroll
        for (int ks = 0; ks < 4; ks++) {       // four k16 steps per BK=64
            int kw = ks * 8;
            uint32_t af[4][4], bf[8][2];
#pragma unroll
            for (int i = 0; i < 4; i++) {
                int r0 = warpM * 64 + i * 16;
                af[i][0] = As[(r0 + gid) * ROWW + kw + tid];
                af[i][1] = As[(r0 + gid + 8) * ROWW + kw + tid];
                af[i][2] = As[(r0 + gid) * ROWW + kw + tid + 4];
                af[i][3] = As[(r0 + gid + 8) * ROWW + kw + tid + 4];
            }
#pragma unroll
            for (int j = 0; j < 8; j++) {
                int c0 = warpN * 64 + j * 8 + gid;
                bf[j][0] = Bs[c0 * ROWW + kw + tid];
                bf[j][1] = Bs[c0 * ROWW + kw + tid + 4];
            }
#pragma unroll
            for (int i = 0; i < 4; i++)
#pragma unroll
                for (int j = 0; j < 8; j++)
                    mma_f16(acc[i][j], af[i][0], af[i][1], af[i][2], af[i][3],
                            bf[j][0], bf[j][1]);
        }
    }

    float norm = 0.17677669529663687f;  // 1/sqrt(32)
#pragma unroll
    for (int i = 0; i < 4; i++) {
#pragma unroll
        for (int j = 0; j < 8; j++) {
            int r0 = bM + warpM * 64 + i * 16 + gid;
            int c0 = warpN * 64 + j * 8 + tid * 2;
#pragma unroll
            for (int e2 = 0; e2 < 2; e2++) {   // row pair: r0, r0+8
                int row = r0 + e2 * 8;
                float v0 = acc[i][j][e2 * 2 + 0];
                float v1 = acc[i][j][e2 * 2 + 1];
                if (type == 4) {
                    out[row * 256 + c0]     = v0 + b_o[c0];
                    out[row * 256 + c0 + 1] = v1 + b_o[c0 + 1];
                } else {
                    if (type == 0) { v0 *= norm; v1 *= norm; }
                    if (type == 3) {
                        v0 = 1.f / (1.f + __expf(-(v0 + b_g[c0])));
                        v1 = 1.f / (1.f + __expf(-(v1 + b_g[c0 + 1])));
                    }
                    __half* Out = (type == 0) ? g_Qh : (type == 1) ? g_Kh
                                : (type == 2) ? g_Vh : g_Gh;
                    int s = row >> 8, rr = row & 255;
                    int h = c0 >> 5, d = c0 & 31;
                    *(__half2*)(Out + ((s * 8 + h) * 256 + rr) * 32 + d) =
                        __floats2half2_rn(v0, v1);
                }
            }
        }
    }
}

// ---------------------------------------------------------------------------
// Kernel 3: tensor-core attention (tf32) reading half Q/K/V/G; gated half out.
// ---------------------------------------------------------------------------
#define ATTN_SMEM_WORDS (9216 + 8320 + 17408 + 256)   // Ks + Vt + Ps + Mb

__global__ void __launch_bounds__(256)
attn_mma_kernel(const float* __restrict__ bias_mask) {
    extern __shared__ uint32_t sm[];
    uint32_t* Ks = sm;                 // [256][36] tf32 K (key, d)
    uint32_t* Vt = sm + 9216;          // [32][260] tf32 V^T (d, key)
    uint32_t* Ps = sm + 17536;         // 8 warps x [32][68] tf32 P
    float*    Mb = (float*)(sm + 34944);  // [256] mask bias

    int s = blockIdx.x, h = blockIdx.y;
    int t = threadIdx.x, lane = t & 31, w = t >> 5;
    int gid = lane >> 2, tid = lane & 3;

    const __half* Qg = g_Qh + (s * 8 + h) * 8192;
    const __half* Kg = g_Kh + (s * 8 + h) * 8192;
    const __half* Vg = g_Vh + (s * 8 + h) * 8192;
    const __half* Gg = g_Gh + (s * 8 + h) * 8192;

    // ---- stage Q (half -> tf32) into Ps region temporarily: Qs[256][36]
    uint32_t* Qs = Ps;
#pragma unroll
    for (int i = t; i < 1024; i += 256) {       // 1024 x 16B = 8192 halves
        uint4 raw = ((const uint4*)Qg)[i];
        int r = i >> 2, d = (i & 3) * 8;
        const __half2* hp = (const __half2*)&raw;
#pragma unroll
        for (int e = 0; e < 4; e++) {
            float2 f = __half22float2(hp[e]);
            Qs[r * 36 + d + e * 2 + 0] = f2tf(f.x);
            Qs[r * 36 + d + e * 2 + 1] = f2tf(f.y);
        }
    }
    __syncthreads();

    uint32_t qf[2][4][4];
#pragma unroll
    for (int i2 = 0; i2 < 2; i2++) {
        int r0 = w * 32 + i2 * 16;
#pragma unroll
        for (int ks = 0; ks < 4; ks++) {
            int kk = ks * 8;
            qf[i2][ks][0] = Qs[(r0 + gid) * 36 + kk + tid];
            qf[i2][ks][1] = Qs[(r0 + gid + 8) * 36 + kk + tid];
            qf[i2][ks][2] = Qs[(r0 + gid) * 36 + kk + tid + 4];
            qf[i2][ks][3] = Qs[(r0 + gid + 8) * 36 + kk + tid + 4];
        }
    }
    __syncthreads();

    // ---- stage K and V^T (half -> tf32)
#pragma unroll
    for (int i = t; i < 1024; i += 256) {
        int r = i >> 2, d = (i & 3) * 8;
        uint4 kraw = ((const uint4*)Kg)[i];
        const __half2* kp = (const __half2*)&kraw;
#pragma unroll
        for (int e = 0; e < 4; e++) {
            float2 f = __half22float2(kp[e]);
            Ks[r * 36 + d + e * 2 + 0] = f2tf(f.x);
            Ks[r * 36 + d + e * 2 + 1] = f2tf(f.y);
        }
        uint4 vraw = ((const uint4*)Vg)[i];
        const __half2* vp = (const __half2*)&vraw;
#pragma unroll
        for (int e = 0; e < 4; e++) {
            float2 f = __half22float2(vp[e]);
            Vt[(d + e * 2 + 0) * 260 + r] = f2tf(f.x);
            Vt[(d + e * 2 + 1) * 260 + r] = f2tf(f.y);
        }
    }
    Mb[t] = (bias_mask[s * 256 + t] - 1.f) * 1e9f;
    __syncthreads();

    const float* biasBase = g_biasT + h * 65536;
    uint32_t* Pw = Ps + w * 2176;   // per-warp private P tile [32][68]

    float oacc[2][4][4];
#pragma unroll
    for (int i2 = 0; i2 < 2; i2++)
#pragma unroll
        for (int j2 = 0; j2 < 4; j2++)
#pragma unroll
            for (int e = 0; e < 4; e++) oacc[i2][j2][e] = 0.f;
    float rs[2][2] = {{0.f, 0.f}, {0.f, 0.f}};

    for (int kc = 0; kc < 256; kc += 64) {
        float sacc[2][8][4];
#pragma unroll
        for (int i2 = 0; i2 < 2; i2++)
#pragma unroll
            for (int j = 0; j < 8; j++)
#pragma unroll
                for (int e = 0; e < 4; e++) sacc[i2][j][e] = 0.f;

#pragma unroll
        for (int ks = 0; ks < 4; ks++) {
            int kk = ks * 8;
            uint32_t bf[8][2];
#pragma unroll
            for (int j = 0; j < 8; j++) {
                int n = kc + j * 8 + gid;
                bf[j][0] = Ks[n * 36 + kk + tid];
                bf[j][1] = Ks[n * 36 + kk + tid + 4];
            }
#pragma unroll
            for (int i2 = 0; i2 < 2; i2++)
#pragma unroll
                for (int j = 0; j < 8; j++)
                    mma_tf32(sacc[i2][j], qf[i2][ks][0], qf[i2][ks][1],
                             qf[i2][ks][2], qf[i2][ks][3], bf[j][0], bf[j][1]);
        }

#pragma unroll
        for (int i2 = 0; i2 < 2; i2++) {
            int qrow = w * 32 + i2 * 16 + gid;
#pragma unroll
            for (int j = 0; j < 8; j++) {
                int col = kc + j * 8 + tid * 2;
                float2 b0 = *(const float2*)(biasBase + qrow * 256 + col);
                float2 b1 = *(const float2*)(biasBase + (qrow + 8) * 256 + col);
                float m0 = Mb[col], m1 = Mb[col + 1];
                float p0 = __expf(sacc[i2][j][0] + b0.x + m0);
                float p1 = __expf(sacc[i2][j][1] + b0.y + m1);
                float p2 = __expf(sacc[i2][j][2] + b1.x + m0);
                float p3 = __expf(sacc[i2][j][3] + b1.y + m1);
                rs[i2][0] += p0 + p1;
                rs[i2][1] += p2 + p3;
                int lr = i2 * 16 + gid, lc = j * 8 + tid * 2;
                Pw[lr * 68 + lc]           = f2tf(p0);
                Pw[lr * 68 + lc + 1]       = f2tf(p1);
                Pw[(lr + 8) * 68 + lc]     = f2tf(p2);
                Pw[(lr + 8) * 68 + lc + 1] = f2tf(p3);
            }
        }
        __syncwarp();

#pragma unroll
        for (int ks2 = 0; ks2 < 8; ks2++) {
            int kk = ks2 * 8;
            uint32_t pf[2][4];
#pragma unroll
            for (int i2 = 0; i2 < 2; i2++) {
                int lr = i2 * 16 + gid;
                pf[i2][0] = Pw[lr * 68 + kk + tid];
                pf[i2][1] = Pw[(lr + 8) * 68 + kk + tid];
                pf[i2][2] = Pw[lr * 68 + kk + tid + 4];
                pf[i2][3] = Pw[(lr + 8) * 68 + kk + tid + 4];
            }
            uint32_t vf[4][2];
#pragma unroll
            for (int j2 = 0; j2 < 4; j2++) {
                int d = j2 * 8 + gid;
                vf[j2][0] = Vt[d * 260 + kc + kk + tid];
                vf[j2][1] = Vt[d * 260 + kc + kk + tid + 4];
            }
#pragma unroll
            for (int i2 = 0; i2 < 2; i2++)
#pragma unroll
                for (int j2 = 0; j2 < 4; j2++)
                    mma_tf32(oacc[i2][j2], pf[i2][0], pf[i2][1],
                             pf[i2][2], pf[i2][3], vf[j2][0], vf[j2][1]);
        }
        __syncwarp();
    }

#pragma unroll
    for (int i2 = 0; i2 < 2; i2++)
#pragma unroll
        for (int rp = 0; rp < 2; rp++) {
            float v = rs[i2][rp];
            v += __shfl_xor_sync(0xffffffffu, v, 1);
            v += __shfl_xor_sync(0xffffffffu, v, 2);
            rs[i2][rp] = 1.f / v;
        }

    // normalize, gate with G, write g_Oh = half(O * G)
    __half* Og = g_Oh + (s * 8 + h) * 8192;
#pragma unroll
    for (int i2 = 0; i2 < 2; i2++) {
        int r0 = w * 32 + i2 * 16 + gid;
#pragma unroll
        for (int j2 = 0; j2 < 4; j2++) {
            int c = j2 * 8 + tid * 2;
            float2 gv0 = __half22float2(*(const __half2*)(Gg + r0 * 32 + c));
            float2 gv1 = __half22float2(*(const __half2*)(Gg + (r0 + 8) * 32 + c));
            ((__half2*)(Og + r0 * 32 + c))[0] = __floats2half2_rn(
                oacc[i2][j2][0] * rs[i2][0] * gv0.x,
                oacc[i2][j2][1] * rs[i2][0] * gv0.y);
            ((__half2*)(Og + (r0 + 8) * 32 + c))[0] = __floats2half2_rn(
                oacc[i2][j2][2] * rs[i2][1] * gv1.x,
                oacc[i2][j2][3] * rs[i2][1] * gv1.y);
        }
    }
}

// ---------------------------------------------------------------------------
extern "C" void kernel_launch(void* const* d_in, const int* in_sizes, int n_in,
                              void* d_out, int out_size) {
    const float* q    = (const float*)d_in[0];
    const float* kv   = (const float*)d_in[1];
    const float* bias = (const float*)d_in[2];
    const float* mask = (const float*)d_in[3];
    const float* w_q  = (const float*)d_in[4];
    const float* w_k  = (const float*)d_in[5];
    const float* w_v  = (const float*)d_in[6];
    const float* w_g  = (const float*)d_in[7];
    const float* b_g  = (const float*)d_in[8];
    const float* w_o  = (const float*)d_in[9];
    const float* b_o  = (const float*)d_in[10];
    float* out = (float*)d_out;

    bias_transpose_kernel<<<(H_DIM * R_DIM * R_DIM + 255) / 256, 256>>>(bias);
    f2h_kernel<<<dim3(8192, 2), 256>>>(q, kv);
    wt_transpose_kernel<<<dim3(8, 8, 5), dim3(32, 8)>>>(w_q, w_k, w_v, w_g, w_o);

    cudaFuncSetAttribute(hgemm_kernel,
                         cudaFuncAttributeMaxDynamicSharedMemorySize,
                         GEMM_SMEM_BYTES);
    // projections: types 0..3
    hgemm_kernel<<<dim3(SR_DIM / 128, 4), 256, GEMM_SMEM_BYTES>>>(
        b_g, b_o, out, 0);

    const int ATTN_SMEM = ATTN_SMEM_WORDS * 4;   // 140800 B
    cudaFuncSetAttribute(attn_mma_kernel,
                         cudaFuncAttributeMaxDynamicSharedMemorySize, ATTN_SMEM);
    attn_mma_kernel<<<dim3(S_DIM, H_DIM), 256, ATTN_SMEM>>>(mask);

    // output projection: type 4
    hgemm_kernel<<<dim3(SR_DIM / 128, 1), 256, GEMM_SMEM_BYTES>>>(
        b_g, b_o, out, 4);
}

// round 13
// speedup vs baseline: 1.4263x; 1.1908x over previous
#include <cuda_runtime.h>
#include <cuda_fp16.h>
#include <math.h>
#include <stdint.h>

#define S_DIM 128
#define R_DIM 256
#define C_DIM 256
#define H_DIM 8
#define D_DIM 32
#define HD_DIM 256
#define SR_DIM (S_DIM * R_DIM)

// Scratch (device globals; allocation-free contract)
__device__ float  g_biasT[H_DIM * R_DIM * R_DIM];        // [h][q][k]
__device__ __half g_qh[SR_DIM * 256];                    // q input, half
__device__ __half g_kvh[SR_DIM * 256];                   // kv input, half
__device__ __half g_Qh[S_DIM * H_DIM * R_DIM * D_DIM];   // [s][h][r][d]
__device__ __half g_Kh[S_DIM * H_DIM * R_DIM * D_DIM];
__device__ __half g_Vh[S_DIM * H_DIM * R_DIM * D_DIM];
__device__ __half g_Gh[S_DIM * H_DIM * R_DIM * D_DIM];
__device__ __half g_Oh[S_DIM * H_DIM * R_DIM * D_DIM];   // gated O
__device__ __half g_WTh[5 * 256 * 256];                  // weights [n][k], half

// ---------------------------------------------------------------------------
// helpers
// ---------------------------------------------------------------------------
__device__ __forceinline__ uint32_t f2tf(float f) {
    uint32_t u;
    asm("cvt.rna.tf32.f32 %0, %1;" : "=r"(u) : "f"(f));
    return u;
}

__device__ __forceinline__ void mma_tf32(float c[4],
                                         uint32_t a0, uint32_t a1,
                                         uint32_t a2, uint32_t a3,
                                         uint32_t b0, uint32_t b1) {
    asm volatile(
        "mma.sync.aligned.m16n8k8.row.col.f32.tf32.tf32.f32 "
        "{%0,%1,%2,%3}, {%4,%5,%6,%7}, {%8,%9}, {%0,%1,%2,%3};"
        : "+f"(c[0]), "+f"(c[1]), "+f"(c[2]), "+f"(c[3])
        : "r"(a0), "r"(a1), "r"(a2), "r"(a3), "r"(b0), "r"(b1));
}

__device__ __forceinline__ void mma_f16(float c[4],
                                        uint32_t a0, uint32_t a1,
                                        uint32_t a2, uint32_t a3,
                                        uint32_t b0, uint32_t b1) {
    asm volatile(
        "mma.sync.aligned.m16n8k16.row.col.f32.f16.f16.f32 "
        "{%0,%1,%2,%3}, {%4,%5,%6,%7}, {%8,%9}, {%0,%1,%2,%3};"
        : "+f"(c[0]), "+f"(c[1]), "+f"(c[2]), "+f"(c[3])
        : "r"(a0), "r"(a1), "r"(a2), "r"(a3), "r"(b0), "r"(b1));
}

__device__ __forceinline__ void cp16(uint32_t smem_addr, const void* gptr) {
    asm volatile("cp.async.cg.shared.global [%0], [%1], 16;"
                 :: "r"(smem_addr), "l"(gptr));
}
__device__ __forceinline__ void cp_commit() {
    asm volatile("cp.async.commit_group;");
}
template <int N>
__device__ __forceinline__ void cp_wait() {
    asm volatile("cp.async.wait_group %0;" :: "n"(N));
}

// fp16 GEMM tiling: block 128(M) x 128(N), BK=64, 8 warps (2M x 4N) of 64x32.
// Row = 64 halves = 32 b32 words, padded stride 36 -> conflict-free frag LDS.
// 2-stage cp.async pipeline, 4 K-chunks.  73.7 KB SMEM, <=128 regs ->
// 2 CTAs/SM = 16 warps/SM = 4 warps/SMSP.
#define ROWW 36
#define A_CH_WORDS (128 * ROWW)   // 4608
#define B_CH_WORDS (128 * ROWW)   // 4608
#define GEMM_SMEM_BYTES (2 * (A_CH_WORDS + B_CH_WORDS) * 4)  // 73728

// ---------------------------------------------------------------------------
// Kernel 1: bias [q][k][h] -> biasT [h][q][k]
// ---------------------------------------------------------------------------
__global__ void bias_transpose_kernel(const float* __restrict__ bias) {
    int idx = blockIdx.x * blockDim.x + threadIdx.x;
    if (idx < H_DIM * R_DIM * R_DIM) {
        int k  = idx & 255;
        int qq = (idx >> 8) & 255;
        int h  = idx >> 16;
        g_biasT[idx] = bias[((qq << 8) + k) * 8 + h];
    }
}

// ---------------------------------------------------------------------------
// Kernel 1b: fp32 -> fp16 conversion of the two activation inputs.
// ---------------------------------------------------------------------------
__global__ void f2h_kernel(const float* __restrict__ qin,
                           const float* __restrict__ kvin) {
    const float* src = blockIdx.y ? kvin : qin;
    __half* dst = blockIdx.y ? g_kvh : g_qh;
    int i = blockIdx.x * 256 + threadIdx.x;     // float4 index
    float4 v = ((const float4*)src)[i];
    __half2* d = (__half2*)(dst + i * 4);
    d[0] = __floats2half2_rn(v.x, v.y);
    d[1] = __floats2half2_rn(v.z, v.w);
}

// ---------------------------------------------------------------------------
// Kernel 1c: transpose five 256x256 weight matrices to K-major [n][k], half.
// ---------------------------------------------------------------------------
__global__ void wt_transpose_kernel(const float* __restrict__ w_q,
                                    const float* __restrict__ w_k,
                                    const float* __restrict__ w_v,
                                    const float* __restrict__ w_g,
                                    const float* __restrict__ w_o) {
    __shared__ float tile[32][33];
    int which = blockIdx.z;
    const float* W = (which == 0) ? w_q : (which == 1) ? w_k
                   : (which == 2) ? w_v : (which == 3) ? w_g : w_o;
    __half* Out = g_WTh + which * 65536;
    int bx = blockIdx.x * 32, by = blockIdx.y * 32;
    int tx = threadIdx.x, ty = threadIdx.y;   // 32 x 8
#pragma unroll
    for (int i = 0; i < 32; i += 8)
        tile[ty + i][tx] = W[(by + ty + i) * 256 + bx + tx];
    __syncthreads();
#pragma unroll
    for (int i = 0; i < 32; i += 8)
        Out[(bx + ty + i) * 256 + by + tx] = __float2half_rn(tile[tx][ty + i]);
}

// ---------------------------------------------------------------------------
// Kernel 2: fp16 m16n8k16 GEMM, block 128x128, BK=64, 2-stage pipeline,
// 2 CTAs/SM.  type 0..3: proj (epilogue norm/sigmoid; half outputs
// [s][h][r][d]).  type 4: outproj (A = g_Oh; out = final fp32 + b_o).
// ---------------------------------------------------------------------------
__global__ void __launch_bounds__(256, 2)
hgemm_kernel(const float* __restrict__ b_g,
             const float* __restrict__ b_o,
             float* __restrict__ out,
             int type_base) {
    extern __shared__ uint32_t smem[];
    uint32_t* Asm = smem;                      // 2 x [128][36]
    uint32_t* Bsm = smem + 2 * A_CH_WORDS;     // 2 x [128][36]

    int type = blockIdx.z + type_base;
    const __half* Ah = (type == 1 || type == 2) ? g_kvh
                     : (type == 4) ? g_Oh : g_qh;
    const __half* Bh = g_WTh + type * 65536;

    int t = threadIdx.x, lane = t & 31, w = t >> 5;
    int warpM = w >> 2, warpN = w & 3;         // 2 x 4 warp grid, tiles 64x32
    int bM = blockIdx.x * 128;
    int bN = blockIdx.y * 128;
    int gid = lane >> 2, tid = lane & 3;

    uint32_t asBase = (uint32_t)__cvta_generic_to_shared(Asm);
    uint32_t bsBase = (uint32_t)__cvta_generic_to_shared(Bsm);

    auto issue = [&](int kt, int buf) {
        int kc = kt * 64;
#pragma unroll
        for (int p = 0; p < 4; p++) {          // A: 128 rows x 8 cp16
            int idx = t + p * 256;
            int r = idx >> 3, c4 = idx & 7;    // c4*8 halves within 64-col row
            const __half* src;
            if (type == 4) {
                int m = bM + r;
                int s = m >> 8, rr = m & 255;
                int head = (kc >> 5) + (c4 >> 2);
                int d0 = (c4 & 3) * 8;
                src = g_Oh + ((s * 8 + head) * 256 + rr) * 32 + d0;
            } else {
                src = Ah + (bM + r) * 256 + kc + c4 * 8;
            }
            cp16(asBase + (buf * A_CH_WORDS + r * ROWW + c4 * 4) * 4, src);
        }
#pragma unroll
        for (int p = 0; p < 4; p++) {          // B: 128 rows x 8 cp16
            int idx = t + p * 256;
            int r = idx >> 3, c4 = idx & 7;
            cp16(bsBase + (buf * B_CH_WORDS + r * ROWW + c4 * 4) * 4,
                 Bh + (bN + r) * 256 + kc + c4 * 8);
        }
        cp_commit();
    };

    float acc[4][4][4];
#pragma unroll
    for (int i = 0; i < 4; i++)
#pragma unroll
        for (int j = 0; j < 4; j++)
#pragma unroll
            for (int r = 0; r < 4; r++) acc[i][j][r] = 0.f;

    issue(0, 0);

    for (int kt = 0; kt < 4; kt++) {
        int cur = kt & 1;
        __syncthreads();                       // all warps done with buf cur
        if (kt < 3) { issue(kt + 1, cur ^ 1); cp_wait<1>(); }
        else        { cp_wait<0>(); }
        __syncthreads();                       // buf cur data visible

        const uint32_t* As = Asm + cur * A_CH_WORDS;
        const uint32_t* Bs = Bsm + cur * B_CH_WORDS;
#pragma unroll
        for (int ks = 0; ks < 4; ks++) {       // four k16 steps per BK=64
            int kw = ks * 8;
            uint32_t af[4][4], bf[4][2];
#pragma unroll
            for (int i = 0; i < 4; i++) {
                int r0 = warpM * 64 + i * 16;
                af[i][0] = As[(r0 + gid) * ROWW + kw + tid];
                af[i][1] = As[(r0 + gid + 8) * ROWW + kw + tid];
                af[i][2] = As[(r0 + gid) * ROWW + kw + tid + 4];
                af[i][3] = As[(r0 + gid + 8) * ROWW + kw + tid + 4];
            }
#pragma unroll
            for (int j = 0; j < 4; j++) {
                int c0 = warpN * 32 + j * 8 + gid;
                bf[j][0] = Bs[c0 * ROWW + kw + tid];
                bf[j][1] = Bs[c0 * ROWW + kw + tid + 4];
            }
#pragma unroll
            for (int i = 0; i < 4; i++)
#pragma unroll
                for (int j = 0; j < 4; j++)
                    mma_f16(acc[i][j], af[i][0], af[i][1], af[i][2], af[i][3],
                            bf[j][0], bf[j][1]);
        }
    }

    float norm = 0.17677669529663687f;  // 1/sqrt(32)
#pragma unroll
    for (int i = 0; i < 4; i++) {
#pragma unroll
        for (int j = 0; j < 4; j++) {
            int r0 = bM + warpM * 64 + i * 16 + gid;
            int c0 = bN + warpN * 32 + j * 8 + tid * 2;
#pragma unroll
            for (int e2 = 0; e2 < 2; e2++) {   // row pair: r0, r0+8
                int row = r0 + e2 * 8;
                float v0 = acc[i][j][e2 * 2 + 0];
                float v1 = acc[i][j][e2 * 2 + 1];
                if (type == 4) {
                    out[row * 256 + c0]     = v0 + b_o[c0];
                    out[row * 256 + c0 + 1] = v1 + b_o[c0 + 1];
                } else {
                    if (type == 0) { v0 *= norm; v1 *= norm; }
                    if (type == 3) {
                        v0 = 1.f / (1.f + __expf(-(v0 + b_g[c0])));
                        v1 = 1.f / (1.f + __expf(-(v1 + b_g[c0 + 1])));
                    }
                    __half* Out = (type == 0) ? g_Qh : (type == 1) ? g_Kh
                                : (type == 2) ? g_Vh : g_Gh;
                    int s = row >> 8, rr = row & 255;
                    int h = c0 >> 5, d = c0 & 31;
                    *(__half2*)(Out + ((s * 8 + h) * 256 + rr) * 32 + d) =
                        __floats2half2_rn(v0, v1);
                }
            }
        }
    }
}

// ---------------------------------------------------------------------------
// Kernel 3: tensor-core attention (tf32) reading half Q/K/V/G; gated half out.
// ---------------------------------------------------------------------------
#define ATTN_SMEM_WORDS (9216 + 8320 + 17408 + 256)   // Ks + Vt + Ps + Mb

__global__ void __launch_bounds__(256)
attn_mma_kernel(const float* __restrict__ bias_mask) {
    extern __shared__ uint32_t sm[];
    uint32_t* Ks = sm;                 // [256][36] tf32 K (key, d)
    uint32_t* Vt = sm + 9216;          // [32][260] tf32 V^T (d, key)
    uint32_t* Ps = sm + 17536;         // 8 warps x [32][68] tf32 P
    float*    Mb = (float*)(sm + 34944);  // [256] mask bias

    int s = blockIdx.x, h = blockIdx.y;
    int t = threadIdx.x, lane = t & 31, w = t >> 5;
    int gid = lane >> 2, tid = lane & 3;

    const __half* Qg = g_Qh + (s * 8 + h) * 8192;
    const __half* Kg = g_Kh + (s * 8 + h) * 8192;
    const __half* Vg = g_Vh + (s * 8 + h) * 8192;
    const __half* Gg = g_Gh + (s * 8 + h) * 8192;

    // ---- stage Q (half -> tf32) into Ps region temporarily: Qs[256][36]
    uint32_t* Qs = Ps;
#pragma unroll
    for (int i = t; i < 1024; i += 256) {       // 1024 x 16B = 8192 halves
        uint4 raw = ((const uint4*)Qg)[i];
        int r = i >> 2, d = (i & 3) * 8;
        const __half2* hp = (const __half2*)&raw;
#pragma unroll
        for (int e = 0; e < 4; e++) {
            float2 f = __half22float2(hp[e]);
            Qs[r * 36 + d + e * 2 + 0] = f2tf(f.x);
            Qs[r * 36 + d + e * 2 + 1] = f2tf(f.y);
        }
    }
    __syncthreads();

    uint32_t qf[2][4][4];
#pragma unroll
    for (int i2 = 0; i2 < 2; i2++) {
        int r0 = w * 32 + i2 * 16;
#pragma unroll
        for (int ks = 0; ks < 4; ks++) {
            int kk = ks * 8;
            qf[i2][ks][0] = Qs[(r0 + gid) * 36 + kk + tid];
            qf[i2][ks][1] = Qs[(r0 + gid + 8) * 36 + kk + tid];
            qf[i2][ks][2] = Qs[(r0 + gid) * 36 + kk + tid + 4];
            qf[i2][ks][3] = Qs[(r0 + gid + 8) * 36 + kk + tid + 4];
        }
    }
    __syncthreads();

    // ---- stage K and V^T (half -> tf32)
#pragma unroll
    for (int i = t; i < 1024; i += 256) {
        int r = i >> 2, d = (i & 3) * 8;
        uint4 kraw = ((const uint4*)Kg)[i];
        const __half2* kp = (const __half2*)&kraw;
#pragma unroll
        for (int e = 0; e < 4; e++) {
            float2 f = __half22float2(kp[e]);
            Ks[r * 36 + d + e * 2 + 0] = f2tf(f.x);
            Ks[r * 36 + d + e * 2 + 1] = f2tf(f.y);
        }
        uint4 vraw = ((const uint4*)Vg)[i];
        const __half2* vp = (const __half2*)&vraw;
#pragma unroll
        for (int e = 0; e < 4; e++) {
            float2 f = __half22float2(vp[e]);
            Vt[(d + e * 2 + 0) * 260 + r] = f2tf(f.x);
            Vt[(d + e * 2 + 1) * 260 + r] = f2tf(f.y);
        }
    }
    Mb[t] = (bias_mask[s * 256 + t] - 1.f) * 1e9f;
    __syncthreads();

    const float* biasBase = g_biasT + h * 65536;
    uint32_t* Pw = Ps + w * 2176;   // per-warp private P tile [32][68]

    float oacc[2][4][4];
#pragma unroll
    for (int i2 = 0; i2 < 2; i2++)
#pragma unroll
        for (int j2 = 0; j2 < 4; j2++)
#pragma unroll
            for (int e = 0; e < 4; e++) oacc[i2][j2][e] = 0.f;
    float rs[2][2] = {{0.f, 0.f}, {0.f, 0.f}};

    for (int kc = 0; kc < 256; kc += 64) {
        float sacc[2][8][4];
#pragma unroll
        for (int i2 = 0; i2 < 2; i2++)
#pragma unroll
            for (int j = 0; j < 8; j++)
#pragma unroll
                for (int e = 0; e < 4; e++) sacc[i2][j][e] = 0.f;

#pragma unroll
        for (int ks = 0; ks < 4; ks++) {
            int kk = ks * 8;
            uint32_t bf[8][2];
#pragma unroll
            for (int j = 0; j < 8; j++) {
                int n = kc + j * 8 + gid;
                bf[j][0] = Ks[n * 36 + kk + tid];
                bf[j][1] = Ks[n * 36 + kk + tid + 4];
            }
#pragma unroll
            for (int i2 = 0; i2 < 2; i2++)
#pragma unroll
                for (int j = 0; j < 8; j++)
                    mma_tf32(sacc[i2][j], qf[i2][ks][0], qf[i2][ks][1],
                             qf[i2][ks][2], qf[i2][ks][3], bf[j][0], bf[j][1]);
        }

#pragma unroll
        for (int i2 = 0; i2 < 2; i2++) {
            int qrow = w * 32 + i2 * 16 + gid;
#pragma unroll
            for (int j = 0; j < 8; j++) {
                int col = kc + j * 8 + tid * 2;
                float2 b0 = *(const float2*)(biasBase + qrow * 256 + col);
                float2 b1 = *(const float2*)(biasBase + (qrow + 8) * 256 + col);
                float m0 = Mb[col], m1 = Mb[col + 1];
                float p0 = __expf(sacc[i2][j][0] + b0.x + m0);
                float p1 = __expf(sacc[i2][j][1] + b0.y + m1);
                float p2 = __expf(sacc[i2][j][2] + b1.x + m0);
                float p3 = __expf(sacc[i2][j][3] + b1.y + m1);
                rs[i2][0] += p0 + p1;
                rs[i2][1] += p2 + p3;
                int lr = i2 * 16 + gid, lc = j * 8 + tid * 2;
                Pw[lr * 68 + lc]           = f2tf(p0);
                Pw[lr * 68 + lc + 1]       = f2tf(p1);
                Pw[(lr + 8) * 68 + lc]     = f2tf(p2);
                Pw[(lr + 8) * 68 + lc + 1] = f2tf(p3);
            }
        }
        __syncwarp();

#pragma unroll
        for (int ks2 = 0; ks2 < 8; ks2++) {
            int kk = ks2 * 8;
            uint32_t pf[2][4];
#pragma unroll
            for (int i2 = 0; i2 < 2; i2++) {
                int lr = i2 * 16 + gid;
                pf[i2][0] = Pw[lr * 68 + kk + tid];
                pf[i2][1] = Pw[(lr + 8) * 68 + kk + tid];
                pf[i2][2] = Pw[lr * 68 + kk + tid + 4];
                pf[i2][3] = Pw[(lr + 8) * 68 + kk + tid + 4];
            }
            uint32_t vf[4][2];
#pragma unroll
            for (int j2 = 0; j2 < 4; j2++) {
                int d = j2 * 8 + gid;
                vf[j2][0] = Vt[d * 260 + kc + kk + tid];
                vf[j2][1] = Vt[d * 260 + kc + kk + tid + 4];
            }
#pragma unroll
            for (int i2 = 0; i2 < 2; i2++)
#pragma unroll
                for (int j2 = 0; j2 < 4; j2++)
                    mma_tf32(oacc[i2][j2], pf[i2][0], pf[i2][1],
                             pf[i2][2], pf[i2][3], vf[j2][0], vf[j2][1]);
        }
        __syncwarp();
    }

#pragma unroll
    for (int i2 = 0; i2 < 2; i2++)
#pragma unroll
        for (int rp = 0; rp < 2; rp++) {
            float v = rs[i2][rp];
            v += __shfl_xor_sync(0xffffffffu, v, 1);
            v += __shfl_xor_sync(0xffffffffu, v, 2);
            rs[i2][rp] = 1.f / v;
        }

    // normalize, gate with G, write g_Oh = half(O * G)
    __half* Og = g_Oh + (s * 8 + h) * 8192;
#pragma unroll
    for (int i2 = 0; i2 < 2; i2++) {
        int r0 = w * 32 + i2 * 16 + gid;
#pragma unroll
        for (int j2 = 0; j2 < 4; j2++) {
            int c = j2 * 8 + tid * 2;
            float2 gv0 = __half22float2(*(const __half2*)(Gg + r0 * 32 + c));
            float2 gv1 = __half22float2(*(const __half2*)(Gg + (r0 + 8) * 32 + c));
            ((__half2*)(Og + r0 * 32 + c))[0] = __floats2half2_rn(
                oacc[i2][j2][0] * rs[i2][0] * gv0.x,
                oacc[i2][j2][1] * rs[i2][0] * gv0.y);
            ((__half2*)(Og + (r0 + 8) * 32 + c))[0] = __floats2half2_rn(
                oacc[i2][j2][2] * rs[i2][1] * gv1.x,
                oacc[i2][j2][3] * rs[i2][1] * gv1.y);
        }
    }
}

// ---------------------------------------------------------------------------
extern "C" void kernel_launch(void* const* d_in, const int* in_sizes, int n_in,
                              void* d_out, int out_size) {
    const float* q    = (const float*)d_in[0];
    const float* kv   = (const float*)d_in[1];
    const float* bias = (const float*)d_in[2];
    const float* mask = (const float*)d_in[3];
    const float* w_q  = (const float*)d_in[4];
    const float* w_k  = (const float*)d_in[5];
    const float* w_v  = (const float*)d_in[6];
    const float* w_g  = (const float*)d_in[7];
    const float* b_g  = (const float*)d_in[8];
    const float* w_o  = (const float*)d_in[9];
    const float* b_o  = (const float*)d_in[10];
    float* out = (float*)d_out;

    bias_transpose_kernel<<<(H_DIM * R_DIM * R_DIM + 255) / 256, 256>>>(bias);
    f2h_kernel<<<dim3(8192, 2), 256>>>(q, kv);
    wt_transpose_kernel<<<dim3(8, 8, 5), dim3(32, 8)>>>(w_q, w_k, w_v, w_g, w_o);

    cudaFuncSetAttribute(hgemm_kernel,
                         cudaFuncAttributeMaxDynamicSharedMemorySize,
                         GEMM_SMEM_BYTES);
    // projections: types 0..3
    hgemm_kernel<<<dim3(SR_DIM / 128, 2, 4), 256, GEMM_SMEM_BYTES>>>(
        b_g, b_o, out, 0);

    const int ATTN_SMEM = ATTN_SMEM_WORDS * 4;   // 140800 B
    cudaFuncSetAttribute(attn_mma_kernel,
                         cudaFuncAttributeMaxDynamicSharedMemorySize, ATTN_SMEM);
    attn_mma_kernel<<<dim3(S_DIM, H_DIM), 256, ATTN_SMEM>>>(mask);

    // output projection: type 4
    hgemm_kernel<<<dim3(SR_DIM / 128, 2, 1), 256, GEMM_SMEM_BYTES>>>(
        b_g, b_o, out, 4);
}

// round 14
// speedup vs baseline: 1.7442x; 1.2229x over previous
#include <cuda_runtime.h>
#include <cuda_fp16.h>
#include <math.h>
#include <stdint.h>

#define S_DIM 128
#define R_DIM 256
#define C_DIM 256
#define H_DIM 8
#define D_DIM 32
#define HD_DIM 256
#define SR_DIM (S_DIM * R_DIM)

// Scratch (device globals; allocation-free contract)
__device__ float  g_biasT[H_DIM * R_DIM * R_DIM];        // [h][q][k]
__device__ __half g_qh[SR_DIM * 256];                    // q input, half
__device__ __half g_kvh[SR_DIM * 256];                   // kv input, half
__device__ __half g_Qh[S_DIM * H_DIM * R_DIM * D_DIM];   // [s][h][r][d]
__device__ __half g_Kh[S_DIM * H_DIM * R_DIM * D_DIM];
__device__ __half g_Vh[S_DIM * H_DIM * R_DIM * D_DIM];
__device__ __half g_Gh[S_DIM * H_DIM * R_DIM * D_DIM];
__device__ __half g_Oh[S_DIM * H_DIM * R_DIM * D_DIM];   // gated O
__device__ __half g_WTh[5 * 256 * 256];                  // weights [n][k], half

// ---------------------------------------------------------------------------
// helpers
// ---------------------------------------------------------------------------
__device__ __forceinline__ void mma_f16(float c[4],
                                        uint32_t a0, uint32_t a1,
                                        uint32_t a2, uint32_t a3,
                                        uint32_t b0, uint32_t b1) {
    asm volatile(
        "mma.sync.aligned.m16n8k16.row.col.f32.f16.f16.f32 "
        "{%0,%1,%2,%3}, {%4,%5,%6,%7}, {%8,%9}, {%0,%1,%2,%3};"
        : "+f"(c[0]), "+f"(c[1]), "+f"(c[2]), "+f"(c[3])
        : "r"(a0), "r"(a1), "r"(a2), "r"(a3), "r"(b0), "r"(b1));
}

__device__ __forceinline__ void cp16(uint32_t smem_addr, const void* gptr) {
    asm volatile("cp.async.cg.shared.global [%0], [%1], 16;"
                 :: "r"(smem_addr), "l"(gptr));
}
__device__ __forceinline__ void cp_commit() {
    asm volatile("cp.async.commit_group;");
}
template <int N>
__device__ __forceinline__ void cp_wait() {
    asm volatile("cp.async.wait_group %0;" :: "n"(N));
}

// fp16 GEMM tiling (unchanged from R13): block 128x128, BK=64, 8 warps of
// 64x32, 2-stage pipeline, 2 CTAs/SM.
#define ROWW 36
#define A_CH_WORDS (128 * ROWW)
#define B_CH_WORDS (128 * ROWW)
#define GEMM_SMEM_BYTES (2 * (A_CH_WORDS + B_CH_WORDS) * 4)  // 73728

// ---------------------------------------------------------------------------
// Kernel 1: bias [q][k][h] -> biasT [h][q][k]
// ---------------------------------------------------------------------------
__global__ void bias_transpose_kernel(const float* __restrict__ bias) {
    int idx = blockIdx.x * blockDim.x + threadIdx.x;
    if (idx < H_DIM * R_DIM * R_DIM) {
        int k  = idx & 255;
        int qq = (idx >> 8) & 255;
        int h  = idx >> 16;
        g_biasT[idx] = bias[((qq << 8) + k) * 8 + h];
    }
}

// ---------------------------------------------------------------------------
// Kernel 1b: fp32 -> fp16 conversion of the two activation inputs.
// ---------------------------------------------------------------------------
__global__ void f2h_kernel(const float* __restrict__ qin,
                           const float* __restrict__ kvin) {
    const float* src = blockIdx.y ? kvin : qin;
    __half* dst = blockIdx.y ? g_kvh : g_qh;
    int i = blockIdx.x * 256 + threadIdx.x;     // float4 index
    float4 v = ((const float4*)src)[i];
    __half2* d = (__half2*)(dst + i * 4);
    d[0] = __floats2half2_rn(v.x, v.y);
    d[1] = __floats2half2_rn(v.z, v.w);
}

// ---------------------------------------------------------------------------
// Kernel 1c: transpose five 256x256 weight matrices to K-major [n][k], half.
// ---------------------------------------------------------------------------
__global__ void wt_transpose_kernel(const float* __restrict__ w_q,
                                    const float* __restrict__ w_k,
                                    const float* __restrict__ w_v,
                                    const float* __restrict__ w_g,
                                    const float* __restrict__ w_o) {
    __shared__ float tile[32][33];
    int which = blockIdx.z;
    const float* W = (which == 0) ? w_q : (which == 1) ? w_k
                   : (which == 2) ? w_v : (which == 3) ? w_g : w_o;
    __half* Out = g_WTh + which * 65536;
    int bx = blockIdx.x * 32, by = blockIdx.y * 32;
    int tx = threadIdx.x, ty = threadIdx.y;   // 32 x 8
#pragma unroll
    for (int i = 0; i < 32; i += 8)
        tile[ty + i][tx] = W[(by + ty + i) * 256 + bx + tx];
    __syncthreads();
#pragma unroll
    for (int i = 0; i < 32; i += 8)
        Out[(bx + ty + i) * 256 + by + tx] = __float2half_rn(tile[tx][ty + i]);
}

// ---------------------------------------------------------------------------
// Kernel 2: fp16 m16n8k16 GEMM (unchanged from R13).
// ---------------------------------------------------------------------------
__global__ void __launch_bounds__(256, 2)
hgemm_kernel(const float* __restrict__ b_g,
             const float* __restrict__ b_o,
             float* __restrict__ out,
             int type_base) {
    extern __shared__ uint32_t smem[];
    uint32_t* Asm = smem;
    uint32_t* Bsm = smem + 2 * A_CH_WORDS;

    int type = blockIdx.z + type_base;
    const __half* Ah = (type == 1 || type == 2) ? g_kvh
                     : (type == 4) ? g_Oh : g_qh;
    const __half* Bh = g_WTh + type * 65536;

    int t = threadIdx.x, lane = t & 31, w = t >> 5;
    int warpM = w >> 2, warpN = w & 3;
    int bM = blockIdx.x * 128;
    int bN = blockIdx.y * 128;
    int gid = lane >> 2, tid = lane & 3;

    uint32_t asBase = (uint32_t)__cvta_generic_to_shared(Asm);
    uint32_t bsBase = (uint32_t)__cvta_generic_to_shared(Bsm);

    auto issue = [&](int kt, int buf) {
        int kc = kt * 64;
#pragma unroll
        for (int p = 0; p < 4; p++) {
            int idx = t + p * 256;
            int r = idx >> 3, c4 = idx & 7;
            const __half* src;
            if (type == 4) {
                int m = bM + r;
                int s = m >> 8, rr = m & 255;
                int head = (kc >> 5) + (c4 >> 2);
                int d0 = (c4 & 3) * 8;
                src = g_Oh + ((s * 8 + head) * 256 + rr) * 32 + d0;
            } else {
                src = Ah + (bM + r) * 256 + kc + c4 * 8;
            }
            cp16(asBase + (buf * A_CH_WORDS + r * ROWW + c4 * 4) * 4, src);
        }
#pragma unroll
        for (int p = 0; p < 4; p++) {
            int idx = t + p * 256;
            int r = idx >> 3, c4 = idx & 7;
            cp16(bsBase + (buf * B_CH_WORDS + r * ROWW + c4 * 4) * 4,
                 Bh + (bN + r) * 256 + kc + c4 * 8);
        }
        cp_commit();
    };

    float acc[4][4][4];
#pragma unroll
    for (int i = 0; i < 4; i++)
#pragma unroll
        for (int j = 0; j < 4; j++)
#pragma unroll
            for (int r = 0; r < 4; r++) acc[i][j][r] = 0.f;

    issue(0, 0);

    for (int kt = 0; kt < 4; kt++) {
        int cur = kt & 1;
        __syncthreads();
        if (kt < 3) { issue(kt + 1, cur ^ 1); cp_wait<1>(); }
        else        { cp_wait<0>(); }
        __syncthreads();

        const uint32_t* As = Asm + cur * A_CH_WORDS;
        const uint32_t* Bs = Bsm + cur * B_CH_WORDS;
#pragma unroll
        for (int ks = 0; ks < 4; ks++) {
            int kw = ks * 8;
            uint32_t af[4][4], bf[4][2];
#pragma unroll
            for (int i = 0; i < 4; i++) {
                int r0 = warpM * 64 + i * 16;
                af[i][0] = As[(r0 + gid) * ROWW + kw + tid];
                af[i][1] = As[(r0 + gid + 8) * ROWW + kw + tid];
                af[i][2] = As[(r0 + gid) * ROWW + kw + tid + 4];
                af[i][3] = As[(r0 + gid + 8) * ROWW + kw + tid + 4];
            }
#pragma unroll
            for (int j = 0; j < 4; j++) {
                int c0 = warpN * 32 + j * 8 + gid;
                bf[j][0] = Bs[c0 * ROWW + kw + tid];
                bf[j][1] = Bs[c0 * ROWW + kw + tid + 4];
            }
#pragma unroll
            for (int i = 0; i < 4; i++)
#pragma unroll
                for (int j = 0; j < 4; j++)
                    mma_f16(acc[i][j], af[i][0], af[i][1], af[i][2], af[i][3],
                            bf[j][0], bf[j][1]);
        }
    }

    float norm = 0.17677669529663687f;  // 1/sqrt(32)
#pragma unroll
    for (int i = 0; i < 4; i++) {
#pragma unroll
        for (int j = 0; j < 4; j++) {
            int r0 = bM + warpM * 64 + i * 16 + gid;
            int c0 = bN + warpN * 32 + j * 8 + tid * 2;
#pragma unroll
            for (int e2 = 0; e2 < 2; e2++) {
                int row = r0 + e2 * 8;
                float v0 = acc[i][j][e2 * 2 + 0];
                float v1 = acc[i][j][e2 * 2 + 1];
                if (type == 4) {
                    out[row * 256 + c0]     = v0 + b_o[c0];
                    out[row * 256 + c0 + 1] = v1 + b_o[c0 + 1];
                } else {
                    if (type == 0) { v0 *= norm; v1 *= norm; }
                    if (type == 3) {
                        v0 = 1.f / (1.f + __expf(-(v0 + b_g[c0])));
                        v1 = 1.f / (1.f + __expf(-(v1 + b_g[c0 + 1])));
                    }
                    __half* Out = (type == 0) ? g_Qh : (type == 1) ? g_Kh
                                : (type == 2) ? g_Vh : g_Gh;
                    int s = row >> 8, rr = row & 255;
                    int h = c0 >> 5, d = c0 & 31;
                    *(__half2*)(Out + ((s * 8 + h) * 256 + rr) * 32 + d) =
                        __floats2half2_rn(v0, v1);
                }
            }
        }
    }
}

// ---------------------------------------------------------------------------
// Kernel 3: fp16 tensor-core attention.  One CTA per (s,h); 8 warps x 32 q.
// S = Q K^T (fp16 mma, fp32 acc), bias+mask+exp fp32, P packed half,
// O += P V (fp16 mma, fp32 acc).  32-key chunks; 58.9 KB SMEM -> 2 CTAs/SM.
// Word strides: Ks/Qs/Ps 20 (bank 20g+t distinct), Vt 132 (bank 4g+t).
// ---------------------------------------------------------------------------
#define AT_KS_W 5120                 // 256 rows x 20 words
#define AT_VT_W 4224                 // 32 rows x 132 words
#define AT_PS_W 5120                 // 8 warps x 32 rows x 20 words
#define AT_SMEM_WORDS (AT_KS_W + AT_VT_W + AT_PS_W + 256)
#define ATTN_SMEM_BYTES (AT_SMEM_WORDS * 4)   // 58880

__global__ void __launch_bounds__(256, 2)
attn_mma_kernel(const float* __restrict__ bias_mask) {
    extern __shared__ uint32_t sm[];
    uint32_t* Ks = sm;                          // half[256][40]
    uint32_t* Vt = sm + AT_KS_W;                // half[32][264]
    uint32_t* Ps = sm + AT_KS_W + AT_VT_W;      // 8 x half[32][40]
    float*    Mb = (float*)(sm + AT_KS_W + AT_VT_W + AT_PS_W);  // [256]

    int s = blockIdx.x, h = blockIdx.y;
    int t = threadIdx.x, lane = t & 31, w = t >> 5;
    int gid = lane >> 2, tid = lane & 3;

    const __half* Qg = g_Qh + (s * 8 + h) * 8192;
    const __half* Kg = g_Kh + (s * 8 + h) * 8192;
    const __half* Vg = g_Vh + (s * 8 + h) * 8192;
    const __half* Gg = g_Gh + (s * 8 + h) * 8192;

    // ---- stage Q (raw half copy) into Ps region temporarily: [256][40]
    uint32_t* Qs = Ps;
#pragma unroll
    for (int i = t; i < 1024; i += 256) {       // 1024 x 8 halves
        uint4 raw = ((const uint4*)Qg)[i];
        int r = i >> 2, c = (i & 3) * 4;        // word col
        Qs[r * 20 + c + 0] = raw.x;
        Qs[r * 20 + c + 1] = raw.y;
        Qs[r * 20 + c + 2] = raw.z;
        Qs[r * 20 + c + 3] = raw.w;
    }
    __syncthreads();

    // ---- Q fragments register-resident: warp w owns rows [w*32, w*32+32)
    uint32_t qf[2][2][4];
#pragma unroll
    for (int i2 = 0; i2 < 2; i2++) {
        int r0 = w * 32 + i2 * 16;
#pragma unroll
        for (int ks = 0; ks < 2; ks++) {
            int kw = ks * 8;
            qf[i2][ks][0] = Qs[(r0 + gid) * 20 + kw + tid];
            qf[i2][ks][1] = Qs[(r0 + gid + 8) * 20 + kw + tid];
            qf[i2][ks][2] = Qs[(r0 + gid) * 20 + kw + tid + 4];
            qf[i2][ks][3] = Qs[(r0 + gid + 8) * 20 + kw + tid + 4];
        }
    }
    __syncthreads();

    // ---- stage K [key][d] and V^T [d][key] (half), mask bias
    __half* VtH = (__half*)Vt;
#pragma unroll
    for (int i = t; i < 1024; i += 256) {
        int r = i >> 2, c = (i & 3) * 4;
        uint4 kraw = ((const uint4*)Kg)[i];
        Ks[r * 20 + c + 0] = kraw.x;
        Ks[r * 20 + c + 1] = kraw.y;
        Ks[r * 20 + c + 2] = kraw.z;
        Ks[r * 20 + c + 3] = kraw.w;
        uint4 vraw = ((const uint4*)Vg)[i];
        int d8 = (i & 3) * 8;
        const __half* vh = (const __half*)&vraw;
#pragma unroll
        for (int e = 0; e < 8; e++)
            VtH[(d8 + e) * 264 + r] = vh[e];
    }
    Mb[t] = (bias_mask[s * 256 + t] - 1.f) * 1e9f;
    __syncthreads();

    const float* biasBase = g_biasT + h * 65536;
    uint32_t* Pw = Ps + w * 640;     // this warp's P tile: half[32][40]

    float oacc[2][4][4];
#pragma unroll
    for (int i2 = 0; i2 < 2; i2++)
#pragma unroll
        for (int j2 = 0; j2 < 4; j2++)
#pragma unroll
            for (int e = 0; e < 4; e++) oacc[i2][j2][e] = 0.f;
    float rs[2][2] = {{0.f, 0.f}, {0.f, 0.f}};

    for (int kc = 0; kc < 256; kc += 32) {
        // ---- S chunk: [32 q x 32 k] via fp16 mma
        float sacc[2][4][4];
#pragma unroll
        for (int i2 = 0; i2 < 2; i2++)
#pragma unroll
            for (int j = 0; j < 4; j++)
#pragma unroll
                for (int e = 0; e < 4; e++) sacc[i2][j][e] = 0.f;

#pragma unroll
        for (int ks = 0; ks < 2; ks++) {
            int kw = ks * 8;
            uint32_t bf[4][2];
#pragma unroll
            for (int j = 0; j < 4; j++) {
                int n = kc + j * 8 + gid;
                bf[j][0] = Ks[n * 20 + kw + tid];
                bf[j][1] = Ks[n * 20 + kw + tid + 4];
            }
#pragma unroll
            for (int i2 = 0; i2 < 2; i2++)
#pragma unroll
                for (int j = 0; j < 4; j++)
                    mma_f16(sacc[i2][j], qf[i2][ks][0], qf[i2][ks][1],
                            qf[i2][ks][2], qf[i2][ks][3], bf[j][0], bf[j][1]);
        }

        // ---- bias + mask + exp; row sums; P -> SMEM (half2)
#pragma unroll
        for (int i2 = 0; i2 < 2; i2++) {
            int qrow = w * 32 + i2 * 16 + gid;
#pragma unroll
            for (int j = 0; j < 4; j++) {
                int col = kc + j * 8 + tid * 2;
                float2 b0 = *(const float2*)(biasBase + qrow * 256 + col);
                float2 b1 = *(const float2*)(biasBase + (qrow + 8) * 256 + col);
                float m0 = Mb[col], m1 = Mb[col + 1];
                float p0 = __expf(sacc[i2][j][0] + b0.x + m0);
                float p1 = __expf(sacc[i2][j][1] + b0.y + m1);
                float p2 = __expf(sacc[i2][j][2] + b1.x + m0);
                float p3 = __expf(sacc[i2][j][3] + b1.y + m1);
                rs[i2][0] += p0 + p1;
                rs[i2][1] += p2 + p3;
                int lr = i2 * 16 + gid;
                __half2 h01 = __floats2half2_rn(p0, p1);
                __half2 h23 = __floats2half2_rn(p2, p3);
                Pw[lr * 20 + 4 * j + tid]       = *(uint32_t*)&h01;
                Pw[(lr + 8) * 20 + 4 * j + tid] = *(uint32_t*)&h23;
            }
        }
        __syncwarp();

        // ---- O += P V (32 keys = 2 k16 steps)
#pragma unroll
        for (int ks2 = 0; ks2 < 2; ks2++) {
            int kw = ks2 * 8;
            uint32_t pf[2][4];
#pragma unroll
            for (int i2 = 0; i2 < 2; i2++) {
                int lr = i2 * 16 + gid;
                pf[i2][0] = Pw[lr * 20 + kw + tid];
                pf[i2][1] = Pw[(lr + 8) * 20 + kw + tid];
                pf[i2][2] = Pw[lr * 20 + kw + tid + 4];
                pf[i2][3] = Pw[(lr + 8) * 20 + kw + tid + 4];
            }
            uint32_t vf[4][2];
#pragma unroll
            for (int j2 = 0; j2 < 4; j2++) {
                int d = j2 * 8 + gid;
                int kwd = (kc + ks2 * 16) >> 1;   // word col in Vt row
                vf[j2][0] = Vt[d * 132 + kwd + tid];
                vf[j2][1] = Vt[d * 132 + kwd + tid + 4];
            }
#pragma unroll
            for (int i2 = 0; i2 < 2; i2++)
#pragma unroll
                for (int j2 = 0; j2 < 4; j2++)
                    mma_f16(oacc[i2][j2], pf[i2][0], pf[i2][1],
                            pf[i2][2], pf[i2][3], vf[j2][0], vf[j2][1]);
        }
        __syncwarp();   // protect Pw before next chunk's writes
    }

    // ---- reduce row sums across tid quad
#pragma unroll
    for (int i2 = 0; i2 < 2; i2++)
#pragma unroll
        for (int rp = 0; rp < 2; rp++) {
            float v = rs[i2][rp];
            v += __shfl_xor_sync(0xffffffffu, v, 1);
            v += __shfl_xor_sync(0xffffffffu, v, 2);
            rs[i2][rp] = 1.f / v;
        }

    // ---- normalize, gate with G, write g_Oh = half(O * G)
    __half* Og = g_Oh + (s * 8 + h) * 8192;
#pragma unroll
    for (int i2 = 0; i2 < 2; i2++) {
        int r0 = w * 32 + i2 * 16 + gid;
#pragma unroll
        for (int j2 = 0; j2 < 4; j2++) {
            int c = j2 * 8 + tid * 2;
            float2 gv0 = __half22float2(*(const __half2*)(Gg + r0 * 32 + c));
            float2 gv1 = __half22float2(*(const __half2*)(Gg + (r0 + 8) * 32 + c));
            ((__half2*)(Og + r0 * 32 + c))[0] = __floats2half2_rn(
                oacc[i2][j2][0] * rs[i2][0] * gv0.x,
                oacc[i2][j2][1] * rs[i2][0] * gv0.y);
            ((__half2*)(Og + (r0 + 8) * 32 + c))[0] = __floats2half2_rn(
                oacc[i2][j2][2] * rs[i2][1] * gv1.x,
                oacc[i2][j2][3] * rs[i2][1] * gv1.y);
        }
    }
}

// ---------------------------------------------------------------------------
extern "C" void kernel_launch(void* const* d_in, const int* in_sizes, int n_in,
                              void* d_out, int out_size) {
    const float* q    = (const float*)d_in[0];
    const float* kv   = (const float*)d_in[1];
    const float* bias = (const float*)d_in[2];
    const float* mask = (const float*)d_in[3];
    const float* w_q  = (const float*)d_in[4];
    const float* w_k  = (const float*)d_in[5];
    const float* w_v  = (const float*)d_in[6];
    const float* w_g  = (const float*)d_in[7];
    const float* b_g  = (const float*)d_in[8];
    const float* w_o  = (const float*)d_in[9];
    const float* b_o  = (const float*)d_in[10];
    float* out = (float*)d_out;

    bias_transpose_kernel<<<(H_DIM * R_DIM * R_DIM + 255) / 256, 256>>>(bias);
    f2h_kernel<<<dim3(8192, 2), 256>>>(q, kv);
    wt_transpose_kernel<<<dim3(8, 8, 5), dim3(32, 8)>>>(w_q, w_k, w_v, w_g, w_o);

    cudaFuncSetAttribute(hgemm_kernel,
                         cudaFuncAttributeMaxDynamicSharedMemorySize,
                         GEMM_SMEM_BYTES);
    // projections: types 0..3
    hgemm_kernel<<<dim3(SR_DIM / 128, 2, 4), 256, GEMM_SMEM_BYTES>>>(
        b_g, b_o, out, 0);

    cudaFuncSetAttribute(attn_mma_kernel,
                         cudaFuncAttributeMaxDynamicSharedMemorySize,
                         ATTN_SMEM_BYTES);
    attn_mma_kernel<<<dim3(S_DIM, H_DIM), 256, ATTN_SMEM_BYTES>>>(mask);

    // output projection: type 4
    hgemm_kernel<<<dim3(SR_DIM / 128, 2, 1), 256, GEMM_SMEM_BYTES>>>(
        b_g, b_o, out, 4);
}